// round 7
// baseline (speedup 1.0000x reference)
#include <cuda_runtime.h>
#include <cuda_bf16.h>
#include <cstdint>

// GCNLayer_EdgeCat on GB300 — R7: software-pipelined edge kernel.
//   We=[We1;We2;We3], Wn=[Wn1;Wn2]:
//     A=nf@We1+be, C=nf@We3, An=nf@Wn1+bn        (k_node_pre)
//     m=ReLU(A[src]+ef@We2+C[dst]); out2=m+ef    (k_edge, scatter mean)
//     out1=ReLU(An+mean@Wn2)+nf                  (k_node_upd)
//   GEMMs: x=hi+lo bf16 split (AhBh+AhBl+AlBh) via mma.m16n8k16.
//   k_edge (512 thr, 1 CTA/SM): ef(t+1) reg-staged + A/C gathers reg-prefetched
//   under the mainloop; 2 bars/tile.

#define H        128
#define NNODE    50000
#define NEDGE    800000
#define BT       64           // rows per tile
#define NT       256          // node kernels: 8 warps (16x64 warp tiles)
#define NTE      512          // edge kernel: 16 warps (16x32 warp tiles)
#define TPB      4            // edge tiles per block
#define STRIDE   136          // bf16 row stride (272B, LDSM conflict-free)
#define TILE_A   (BT * STRIDE)
#define TILE_W   (H * STRIDE)

__device__ float g_A  [(size_t)NNODE * H];
__device__ float g_C  [(size_t)NNODE * H];
__device__ float g_An [(size_t)NNODE * H];
__device__ float g_sum[(size_t)NNODE * H];
__device__ float g_cnt[NNODE];
// 5 weights (We1,We2,We3,Wn1,Wn2): [k][n] row-major bf16, hi image then lo image.
__device__ __nv_bfloat16 g_Wimg[5 * 2 * H * H];

// ---------- PTX helpers ----------
__device__ __forceinline__ uint32_t smem_u32(const void* p) {
    return (uint32_t)__cvta_generic_to_shared(p);
}
__device__ __forceinline__ void ldsm_x4(uint32_t a[4], uint32_t addr) {
    asm volatile("ldmatrix.sync.aligned.m8n8.x4.shared.b16 {%0,%1,%2,%3}, [%4];"
                 : "=r"(a[0]), "=r"(a[1]), "=r"(a[2]), "=r"(a[3]) : "r"(addr));
}
__device__ __forceinline__ void ldsm_x4_t(uint32_t b[4], uint32_t addr) {
    asm volatile("ldmatrix.sync.aligned.m8n8.x4.trans.shared.b16 {%0,%1,%2,%3}, [%4];"
                 : "=r"(b[0]), "=r"(b[1]), "=r"(b[2]), "=r"(b[3]) : "r"(addr));
}
__device__ __forceinline__ void mma16816(float c[4], const uint32_t a[4], const uint32_t b[2]) {
    asm volatile("mma.sync.aligned.m16n8k16.row.col.f32.bf16.bf16.f32 "
                 "{%0,%1,%2,%3}, {%4,%5,%6,%7}, {%8,%9}, {%0,%1,%2,%3};"
                 : "+f"(c[0]), "+f"(c[1]), "+f"(c[2]), "+f"(c[3])
                 : "r"(a[0]), "r"(a[1]), "r"(a[2]), "r"(a[3]), "r"(b[0]), "r"(b[1]));
}
__device__ __forceinline__ void red_add_v2(float* p, float x, float y) {
    asm volatile("red.global.add.v2.f32 [%0], {%1, %2};" :: "l"(p), "f"(x), "f"(y) : "memory");
}

// Split a float4 into hi/lo bf16 pairs and store at element offset off (even).
__device__ __forceinline__ void split_store(__nv_bfloat16* hi, __nv_bfloat16* lo,
                                            int off, float4 v) {
    __nv_bfloat16 h0 = __float2bfloat16(v.x), h1 = __float2bfloat16(v.y);
    __nv_bfloat16 h2 = __float2bfloat16(v.z), h3 = __float2bfloat16(v.w);
    __nv_bfloat16 l0 = __float2bfloat16(v.x - __bfloat162float(h0));
    __nv_bfloat16 l1 = __float2bfloat16(v.y - __bfloat162float(h1));
    __nv_bfloat16 l2 = __float2bfloat16(v.z - __bfloat162float(h2));
    __nv_bfloat16 l3 = __float2bfloat16(v.w - __bfloat162float(h3));
    *(__nv_bfloat162*)(hi + off)     = __nv_bfloat162{h0, h1};
    *(__nv_bfloat162*)(hi + off + 2) = __nv_bfloat162{h2, h3};
    *(__nv_bfloat162*)(lo + off)     = __nv_bfloat162{l0, l1};
    *(__nv_bfloat162*)(lo + off + 2) = __nv_bfloat162{l2, l3};
}

// 8-warp core: warp tile 16 rows x 64 cols (node kernels).
__device__ __forceinline__ void mma_core(const __nv_bfloat16* sXhi, const __nv_bfloat16* sXlo,
                                         const __nv_bfloat16* sWhi, const __nv_bfloat16* sWlo,
                                         int lane, int warp, float acc[8][4]) {
    uint32_t xhi = smem_u32(sXhi), xlo = smem_u32(sXlo);
    uint32_t whi = smem_u32(sWhi), wlo = smem_u32(sWlo);
    int r0 = (warp & 3) * 16, c0 = (warp >> 2) * 64;
    uint32_t aoff = (uint32_t)((r0 + (lane & 15)) * STRIDE + ((lane >> 4) << 3)) * 2;
    uint32_t boff = (uint32_t)((lane & 15) * STRIDE + c0 + ((lane >> 4) << 3)) * 2;
#pragma unroll
    for (int k0 = 0; k0 < H; k0 += 16) {
        uint32_t ah[4], al[4];
        ldsm_x4(ah, xhi + aoff + k0 * 2);
        ldsm_x4(al, xlo + aoff + k0 * 2);
#pragma unroll
        for (int ntp = 0; ntp < 4; ntp++) {
            uint32_t bh[4], bl[4];
            uint32_t bo = boff + (uint32_t)(k0 * STRIDE + ntp * 16) * 2;
            ldsm_x4_t(bh, whi + bo);
            ldsm_x4_t(bl, wlo + bo);
            mma16816(acc[2 * ntp],     ah, bh + 0);
            mma16816(acc[2 * ntp + 1], ah, bh + 2);
            mma16816(acc[2 * ntp],     ah, bl + 0);
            mma16816(acc[2 * ntp + 1], ah, bl + 2);
            mma16816(acc[2 * ntp],     al, bh + 0);
            mma16816(acc[2 * ntp + 1], al, bh + 2);
        }
    }
}

// 16-warp core: warp tile 16 rows x 32 cols (edge kernel).
__device__ __forceinline__ void mma_core32(const __nv_bfloat16* sXhi, const __nv_bfloat16* sXlo,
                                           const __nv_bfloat16* sWhi, const __nv_bfloat16* sWlo,
                                           int lane, int warp, float acc[4][4]) {
    uint32_t xhi = smem_u32(sXhi), xlo = smem_u32(sXlo);
    uint32_t whi = smem_u32(sWhi), wlo = smem_u32(sWlo);
    int r0 = (warp & 3) * 16, c0 = (warp >> 2) * 32;
    uint32_t aoff = (uint32_t)((r0 + (lane & 15)) * STRIDE + ((lane >> 4) << 3)) * 2;
    uint32_t boff = (uint32_t)((lane & 15) * STRIDE + c0 + ((lane >> 4) << 3)) * 2;
#pragma unroll
    for (int k0 = 0; k0 < H; k0 += 16) {
        uint32_t ah[4], al[4];
        ldsm_x4(ah, xhi + aoff + k0 * 2);
        ldsm_x4(al, xlo + aoff + k0 * 2);
#pragma unroll
        for (int ntp = 0; ntp < 2; ntp++) {
            uint32_t bh[4], bl[4];
            uint32_t bo = boff + (uint32_t)(k0 * STRIDE + ntp * 16) * 2;
            ldsm_x4_t(bh, whi + bo);
            ldsm_x4_t(bl, wlo + bo);
            mma16816(acc[2 * ntp],     ah, bh + 0);
            mma16816(acc[2 * ntp + 1], ah, bh + 2);
            mma16816(acc[2 * ntp],     ah, bl + 0);
            mma16816(acc[2 * ntp + 1], ah, bl + 2);
            mma16816(acc[2 * ntp],     al, bh + 0);
            mma16816(acc[2 * ntp + 1], al, bh + 2);
        }
    }
}

// Copy a prepped W image pair (hi+lo, [k][n] 128x128 bf16) into padded smem.
__device__ __forceinline__ void fill_W(__nv_bfloat16* sWhi, __nv_bfloat16* sWlo,
                                       int wsel, int t, int nthr) {
    const uint4* hi4 = (const uint4*)(g_Wimg + (size_t)wsel * 2 * H * H);
    const uint4* lo4 = hi4 + (H * H / 8);
    for (int i = t; i < H * H / 8; i += nthr) {       // 2048 uint4 per image
        int row = i >> 4, c8 = (i & 15) * 8;
        *(uint4*)(sWhi + row * STRIDE + c8) = hi4[i];
        *(uint4*)(sWlo + row * STRIDE + c8) = lo4[i];
    }
}

// ---- k_prep: split weights into bf16 hi/lo [k][n] images (once) ----
__global__ void k_prep(const float* __restrict__ We, const float* __restrict__ Wn) {
    int idx = blockIdx.x * blockDim.x + threadIdx.x;
    if (idx >= 5 * H * H) return;
    int w = idx / (H * H), r = idx % (H * H);
    const float* src = (w < 3) ? (We + w * H * H) : (Wn + (w - 3) * H * H);
    float v = src[r];
    __nv_bfloat16 hi = __float2bfloat16(v);
    __nv_bfloat16 lo = __float2bfloat16(v - __bfloat162float(hi));
    g_Wimg[(size_t)w * 2 * H * H + r] = hi;
    g_Wimg[(size_t)w * 2 * H * H + H * H + r] = lo;
}

// ---- k_node_pre: zero sums; A=nf@We1+be, C=nf@We3, An=nf@Wn1+bn ----
__global__ __launch_bounds__(NT, 2)
void k_node_pre(const float* __restrict__ nf,
                const float* __restrict__ be, const float* __restrict__ bn) {
    extern __shared__ __align__(16) __nv_bfloat16 sm[];
    __nv_bfloat16* sXhi = sm;
    __nv_bfloat16* sXlo = sm + TILE_A;
    __nv_bfloat16* sWhi = sm + 2 * TILE_A;
    __nv_bfloat16* sWlo = sm + 2 * TILE_A + TILE_W;
    int t = threadIdx.x, lane = t & 31, warp = t >> 5;
    int nb = blockIdx.x * BT;

    for (int i = t; i < BT * 32; i += NT) {
        int n = nb + (i >> 5);
        if (n < NNODE) ((float4*)g_sum)[(size_t)n * 32 + (i & 31)] = make_float4(0.f, 0.f, 0.f, 0.f);
    }
    if (t < BT && nb + t < NNODE) g_cnt[nb + t] = 0.f;

    for (int i = t; i < BT * 32; i += NT) {
        int n = nb + (i >> 5);
        float4 v = make_float4(0.f, 0.f, 0.f, 0.f);
        if (n < NNODE) v = ((const float4*)nf)[(size_t)n * 32 + (i & 31)];
        split_store(sXhi, sXlo, (i >> 5) * STRIDE + (i & 31) * 4, v);
    }

    const int    wsel[3] = {0, 2, 3};
    float*       Od[3]   = {g_A, g_C, g_An};
    const float* bias[3] = {be, (const float*)0, bn};

    int rq = (lane >> 2), cb = (warp >> 2) * 64 + (lane & 3) * 2;
    int lr0 = (warp & 3) * 16 + rq, lr1 = lr0 + 8;

    for (int ph = 0; ph < 3; ph++) {
        __syncthreads();
        fill_W(sWhi, sWlo, wsel[ph], t, NT);
        __syncthreads();

        float acc[8][4];
#pragma unroll
        for (int i = 0; i < 8; i++) acc[i][0] = acc[i][1] = acc[i][2] = acc[i][3] = 0.f;
        mma_core(sXhi, sXlo, sWhi, sWlo, lane, warp, acc);

        float* O = Od[ph];
        bool w0 = (nb + lr0) < NNODE, w1 = (nb + lr1) < NNODE;
#pragma unroll
        for (int nt = 0; nt < 8; nt++) {
            int col = cb + nt * 8;
            float2 b = make_float2(0.f, 0.f);
            if (bias[ph]) b = *(const float2*)&bias[ph][col];
            if (w0) *(float2*)&O[(size_t)(nb + lr0) * H + col] =
                        make_float2(acc[nt][0] + b.x, acc[nt][1] + b.y);
            if (w1) *(float2*)&O[(size_t)(nb + lr1) * H + col] =
                        make_float2(acc[nt][2] + b.x, acc[nt][3] + b.y);
        }
    }
}

// ---- k_edge: pipelined. m=ReLU(A[src]+ef@We2+C[dst]); out2=m+ef; scatter mean ----
__global__ __launch_bounds__(NTE, 1)
void k_edge(const float* __restrict__ ef,
            const int* __restrict__ src, const int* __restrict__ dst,
            float* __restrict__ out2) {
    extern __shared__ __align__(16) __nv_bfloat16 sm[];
    __nv_bfloat16* sXhi = sm;
    __nv_bfloat16* sXlo = sm + TILE_A;
    __nv_bfloat16* sWhi = sm + 2 * TILE_A;
    __nv_bfloat16* sWlo = sm + 2 * TILE_A + TILE_W;
    int* s_src = (int*)(sm + 2 * TILE_A + 2 * TILE_W);    // TPB*BT ints
    int* s_dst = s_src + TPB * BT;
    int t = threadIdx.x, lane = t & 31, warp = t >> 5;
    int ebase = blockIdx.x * (TPB * BT);

    // preload all tile indices for this block
    if (t < TPB * BT) s_src[t] = src[ebase + t];
    else              s_dst[t - TPB * BT] = dst[ebase + (t - TPB * BT)];

    // stage ef tile 0 into regs; fill We2 once
    const float4* ef4 = (const float4*)(ef + (size_t)ebase * H);
    float4 efreg[4];
#pragma unroll
    for (int j = 0; j < 4; j++) efreg[j] = ef4[t + j * NTE];
    fill_W(sWhi, sWlo, 1, t, NTE);
    __syncthreads();

    int rq = lane >> 2, cbase = (warp >> 2) * 32 + (lane & 3) * 2;
    int lr0 = (warp & 3) * 16 + rq, lr1 = lr0 + 8;

    for (int tt = 0; tt < TPB; tt++) {
        // STS staged ef(tt) -> sX (buffer free: bottom sync of prev iter)
#pragma unroll
        for (int j = 0; j < 4; j++) {
            int i = t + j * NTE;
            split_store(sXhi, sXlo, (i >> 5) * STRIDE + (i & 31) * 4, efreg[j]);
        }

        // prefetch epilogue gathers for tile tt (hidden under mainloop)
        int e0 = tt * BT + lr0, e1 = tt * BT + lr1;
        int s0 = s_src[e0], d0 = s_dst[e0];
        int s1 = s_src[e1], d1 = s_dst[e1];
        float2 av0[4], cv0[4], av1[4], cv1[4];
#pragma unroll
        for (int nt = 0; nt < 4; nt++) {
            int col = cbase + nt * 8;
            av0[nt] = *(const float2*)&g_A[(size_t)s0 * H + col];
            cv0[nt] = *(const float2*)&g_C[(size_t)d0 * H + col];
            av1[nt] = *(const float2*)&g_A[(size_t)s1 * H + col];
            cv1[nt] = *(const float2*)&g_C[(size_t)d1 * H + col];
        }
        // stage ef(tt+1)
        if (tt + 1 < TPB) {
#pragma unroll
            for (int j = 0; j < 4; j++)
                efreg[j] = ef4[(tt + 1) * (BT * 32) + t + j * NTE];
        }
        __syncthreads();   // sX ready

        float acc[4][4];
#pragma unroll
        for (int i = 0; i < 4; i++) acc[i][0] = acc[i][1] = acc[i][2] = acc[i][3] = 0.f;
        mma_core32(sXhi, sXlo, sWhi, sWlo, lane, warp, acc);

        if ((warp >> 2) == 0 && (lane & 3) == 0) {
            atomicAdd(&g_cnt[d0], 1.f); atomicAdd(&g_cnt[d1], 1.f);
        }

#pragma unroll
        for (int nt = 0; nt < 4; nt++) {
            int col = cbase + nt * 8;
            {   // row lr0
                float m0 = fmaxf(acc[nt][0] + av0[nt].x + cv0[nt].x, 0.f);
                float m1 = fmaxf(acc[nt][1] + av0[nt].y + cv0[nt].y, 0.f);
                __nv_bfloat162 eh = *(__nv_bfloat162*)&sXhi[lr0 * STRIDE + col];
                __nv_bfloat162 el = *(__nv_bfloat162*)&sXlo[lr0 * STRIDE + col];
                *(float2*)&out2[(size_t)(ebase + e0) * H + col] =
                    make_float2(m0 + __bfloat162float(eh.x) + __bfloat162float(el.x),
                                m1 + __bfloat162float(eh.y) + __bfloat162float(el.y));
                red_add_v2(&g_sum[(size_t)d0 * H + col], m0, m1);
            }
            {   // row lr1
                float m0 = fmaxf(acc[nt][2] + av1[nt].x + cv1[nt].x, 0.f);
                float m1 = fmaxf(acc[nt][3] + av1[nt].y + cv1[nt].y, 0.f);
                __nv_bfloat162 eh = *(__nv_bfloat162*)&sXhi[lr1 * STRIDE + col];
                __nv_bfloat162 el = *(__nv_bfloat162*)&sXlo[lr1 * STRIDE + col];
                *(float2*)&out2[(size_t)(ebase + e1) * H + col] =
                    make_float2(m0 + __bfloat162float(eh.x) + __bfloat162float(el.x),
                                m1 + __bfloat162float(eh.y) + __bfloat162float(el.y));
                red_add_v2(&g_sum[(size_t)d1 * H + col], m0, m1);
            }
        }
        __syncthreads();   // sX free for next STS
    }
}

// ---- k_node_upd: out1 = ReLU(An + (sum/max(cnt,1))@Wn2) + nf ----
__global__ __launch_bounds__(NT, 2)
void k_node_upd(const float* __restrict__ nf, float* __restrict__ out1) {
    extern __shared__ __align__(16) __nv_bfloat16 sm[];
    __nv_bfloat16* sXhi = sm;
    __nv_bfloat16* sXlo = sm + TILE_A;
    __nv_bfloat16* sWhi = sm + 2 * TILE_A;
    __nv_bfloat16* sWlo = sm + 2 * TILE_A + TILE_W;
    int t = threadIdx.x, lane = t & 31, warp = t >> 5;
    int nb = blockIdx.x * BT;

    for (int i = t; i < BT * 32; i += NT) {
        int n = nb + (i >> 5);
        float4 v = make_float4(0.f, 0.f, 0.f, 0.f);
        if (n < NNODE) {
            v = ((const float4*)g_sum)[(size_t)n * 32 + (i & 31)];
            float inv = 1.0f / fmaxf(g_cnt[n], 1.0f);
            v.x *= inv; v.y *= inv; v.z *= inv; v.w *= inv;
        }
        split_store(sXhi, sXlo, (i >> 5) * STRIDE + (i & 31) * 4, v);
    }
    fill_W(sWhi, sWlo, 4, t, NT);                    // Wn2
    __syncthreads();

    float acc[8][4];
#pragma unroll
    for (int i = 0; i < 8; i++) acc[i][0] = acc[i][1] = acc[i][2] = acc[i][3] = 0.f;
    mma_core(sXhi, sXlo, sWhi, sWlo, lane, warp, acc);

    int rq = lane >> 2, cb = (warp >> 2) * 64 + (lane & 3) * 2;
    int lr0 = (warp & 3) * 16 + rq, lr1 = lr0 + 8;
    bool w0 = (nb + lr0) < NNODE, w1 = (nb + lr1) < NNODE;
#pragma unroll
    for (int nt = 0; nt < 8; nt++) {
        int col = cb + nt * 8;
        if (w0) {
            float2 an = *(const float2*)&g_An[(size_t)(nb + lr0) * H + col];
            float2 nv = *(const float2*)&nf[(size_t)(nb + lr0) * H + col];
            *(float2*)&out1[(size_t)(nb + lr0) * H + col] =
                make_float2(fmaxf(acc[nt][0] + an.x, 0.f) + nv.x,
                            fmaxf(acc[nt][1] + an.y, 0.f) + nv.y);
        }
        if (w1) {
            float2 an = *(const float2*)&g_An[(size_t)(nb + lr1) * H + col];
            float2 nv = *(const float2*)&nf[(size_t)(nb + lr1) * H + col];
            *(float2*)&out1[(size_t)(nb + lr1) * H + col] =
                make_float2(fmaxf(acc[nt][2] + an.x, 0.f) + nv.x,
                            fmaxf(acc[nt][3] + an.y, 0.f) + nv.y);
        }
    }
}

extern "C" void kernel_launch(void* const* d_in, const int* in_sizes, int n_in,
                              void* d_out, int out_size) {
    const float* nf  = (const float*)d_in[0];
    const float* ef  = (const float*)d_in[1];
    const int*   src = (const int*)d_in[2];
    const int*   dst = (const int*)d_in[3];
    const float* We  = (const float*)d_in[4];
    const float* be  = (const float*)d_in[5];
    const float* Wn  = (const float*)d_in[6];
    const float* bn  = (const float*)d_in[7];
    float* out1 = (float*)d_out;                    // [N,H]
    float* out2 = out1 + (size_t)NNODE * H;         // [E,H]

    const int smem_gemm = (2 * TILE_A + 2 * TILE_W) * (int)sizeof(__nv_bfloat16); // 104448
    const int smem_edge = smem_gemm + 2 * TPB * BT * (int)sizeof(int);            // +2048
    cudaFuncSetAttribute(k_node_pre, cudaFuncAttributeMaxDynamicSharedMemorySize, smem_gemm);
    cudaFuncSetAttribute(k_edge,     cudaFuncAttributeMaxDynamicSharedMemorySize, smem_edge);
    cudaFuncSetAttribute(k_node_upd, cudaFuncAttributeMaxDynamicSharedMemorySize, smem_gemm);

    k_prep<<<(5 * H * H + 255) / 256, 256>>>(We, Wn);
    k_node_pre<<<(NNODE + BT - 1) / BT, NT, smem_gemm>>>(nf, be, bn);
    k_edge<<<NEDGE / (BT * TPB), NTE, smem_edge>>>(ef, src, dst, out2);
    k_node_upd<<<(NNODE + BT - 1) / BT, NT, smem_gemm>>>(nf, out1);
}

// round 8
// speedup vs baseline: 1.4586x; 1.4586x over previous
#include <cuda_runtime.h>
#include <cuda_bf16.h>
#include <cstdint>

// GCNLayer_EdgeCat on GB300 — R8: R5 structure + coalesced staged epilogue.
//   We=[We1;We2;We3], Wn=[Wn1;Wn2]:
//     A=nf@We1+be, C=nf@We3, An=nf@Wn1+bn        (k_node_pre)
//     m=ReLU(A[src]+ef@We2+C[dst]); out2=m+ef    (k_edge, scatter mean)
//     out1=ReLU(An+mean@Wn2)+nf                  (k_node_upd)
//   GEMMs: x=hi+lo bf16 split (AhBh+AhBl+AlBh) via mma.m16n8k16.
//   k_edge: acc staged through smem in 16-row chunks -> epilogue threads own
//   8 contiguous cols => LDG.128/STG.128/red.v4 fully coalesced.

#define H        128
#define NNODE    50000
#define NEDGE    800000
#define BT       64           // rows per tile
#define NT       256          // 8 warps: warp = 16 rows x 64 cols
#define TPB      8            // edge tiles per block (last block: tail guard)
#define NTILES   (NEDGE / BT) // 12500
#define STRIDE   136          // bf16 row stride (272B, LDSM conflict-free)
#define SSTRIDE  136          // f32 stage stride (conflict-free STS.64)
#define TILE_A   (BT * STRIDE)
#define TILE_W   (H * STRIDE)

__device__ float g_A  [(size_t)NNODE * H];
__device__ float g_C  [(size_t)NNODE * H];
__device__ float g_An [(size_t)NNODE * H];
__device__ float g_sum[(size_t)NNODE * H];
__device__ float g_cnt[NNODE];
// 5 weights (We1,We2,We3,Wn1,Wn2): [k][n] row-major bf16, hi image then lo image.
__device__ __nv_bfloat16 g_Wimg[5 * 2 * H * H];

// ---------- PTX helpers ----------
__device__ __forceinline__ uint32_t smem_u32(const void* p) {
    return (uint32_t)__cvta_generic_to_shared(p);
}
__device__ __forceinline__ void ldsm_x4(uint32_t a[4], uint32_t addr) {
    asm volatile("ldmatrix.sync.aligned.m8n8.x4.shared.b16 {%0,%1,%2,%3}, [%4];"
                 : "=r"(a[0]), "=r"(a[1]), "=r"(a[2]), "=r"(a[3]) : "r"(addr));
}
__device__ __forceinline__ void ldsm_x4_t(uint32_t b[4], uint32_t addr) {
    asm volatile("ldmatrix.sync.aligned.m8n8.x4.trans.shared.b16 {%0,%1,%2,%3}, [%4];"
                 : "=r"(b[0]), "=r"(b[1]), "=r"(b[2]), "=r"(b[3]) : "r"(addr));
}
__device__ __forceinline__ void mma16816(float c[4], const uint32_t a[4], const uint32_t b[2]) {
    asm volatile("mma.sync.aligned.m16n8k16.row.col.f32.bf16.bf16.f32 "
                 "{%0,%1,%2,%3}, {%4,%5,%6,%7}, {%8,%9}, {%0,%1,%2,%3};"
                 : "+f"(c[0]), "+f"(c[1]), "+f"(c[2]), "+f"(c[3])
                 : "r"(a[0]), "r"(a[1]), "r"(a[2]), "r"(a[3]), "r"(b[0]), "r"(b[1]));
}
__device__ __forceinline__ void red_add_v4(float* p, float4 v) {
    asm volatile("red.global.add.v4.f32 [%0], {%1, %2, %3, %4};"
                 :: "l"(p), "f"(v.x), "f"(v.y), "f"(v.z), "f"(v.w) : "memory");
}

// Split a float4 into hi/lo bf16 pairs and store at element offset off (even).
__device__ __forceinline__ void split_store(__nv_bfloat16* hi, __nv_bfloat16* lo,
                                            int off, float4 v) {
    __nv_bfloat16 h0 = __float2bfloat16(v.x), h1 = __float2bfloat16(v.y);
    __nv_bfloat16 h2 = __float2bfloat16(v.z), h3 = __float2bfloat16(v.w);
    __nv_bfloat16 l0 = __float2bfloat16(v.x - __bfloat162float(h0));
    __nv_bfloat16 l1 = __float2bfloat16(v.y - __bfloat162float(h1));
    __nv_bfloat16 l2 = __float2bfloat16(v.z - __bfloat162float(h2));
    __nv_bfloat16 l3 = __float2bfloat16(v.w - __bfloat162float(h3));
    *(__nv_bfloat162*)(hi + off)     = __nv_bfloat162{h0, h1};
    *(__nv_bfloat162*)(hi + off + 2) = __nv_bfloat162{h2, h3};
    *(__nv_bfloat162*)(lo + off)     = __nv_bfloat162{l0, l1};
    *(__nv_bfloat162*)(lo + off + 2) = __nv_bfloat162{l2, l3};
}

// 8-warp core: warp tile 16 rows x 64 cols.
// acc[nt][0..1]: row (warp&3)*16 + lane>>2,   col (warp>>2)*64 + nt*8 + (lane&3)*2
// acc[nt][2..3]: row +8, same cols.
__device__ __forceinline__ void mma_core(const __nv_bfloat16* sXhi, const __nv_bfloat16* sXlo,
                                         const __nv_bfloat16* sWhi, const __nv_bfloat16* sWlo,
                                         int lane, int warp, float acc[8][4]) {
    uint32_t xhi = smem_u32(sXhi), xlo = smem_u32(sXlo);
    uint32_t whi = smem_u32(sWhi), wlo = smem_u32(sWlo);
    int r0 = (warp & 3) * 16, c0 = (warp >> 2) * 64;
    uint32_t aoff = (uint32_t)((r0 + (lane & 15)) * STRIDE + ((lane >> 4) << 3)) * 2;
    uint32_t boff = (uint32_t)((lane & 15) * STRIDE + c0 + ((lane >> 4) << 3)) * 2;
#pragma unroll
    for (int k0 = 0; k0 < H; k0 += 16) {
        uint32_t ah[4], al[4];
        ldsm_x4(ah, xhi + aoff + k0 * 2);
        ldsm_x4(al, xlo + aoff + k0 * 2);
#pragma unroll
        for (int ntp = 0; ntp < 4; ntp++) {
            uint32_t bh[4], bl[4];
            uint32_t bo = boff + (uint32_t)(k0 * STRIDE + ntp * 16) * 2;
            ldsm_x4_t(bh, whi + bo);
            ldsm_x4_t(bl, wlo + bo);
            mma16816(acc[2 * ntp],     ah, bh + 0);
            mma16816(acc[2 * ntp + 1], ah, bh + 2);
            mma16816(acc[2 * ntp],     ah, bl + 0);
            mma16816(acc[2 * ntp + 1], ah, bl + 2);
            mma16816(acc[2 * ntp],     al, bh + 0);
            mma16816(acc[2 * ntp + 1], al, bh + 2);
        }
    }
}

// Copy a prepped W image pair (hi+lo, [k][n] 128x128 bf16) into padded smem.
__device__ __forceinline__ void fill_W(__nv_bfloat16* sWhi, __nv_bfloat16* sWlo,
                                       int wsel, int t, int nthr) {
    const uint4* hi4 = (const uint4*)(g_Wimg + (size_t)wsel * 2 * H * H);
    const uint4* lo4 = hi4 + (H * H / 8);
    for (int i = t; i < H * H / 8; i += nthr) {       // 2048 uint4 per image
        int row = i >> 4, c8 = (i & 15) * 8;
        *(uint4*)(sWhi + row * STRIDE + c8) = hi4[i];
        *(uint4*)(sWlo + row * STRIDE + c8) = lo4[i];
    }
}

// ---- k_prep: split weights into bf16 hi/lo [k][n] images (once) ----
__global__ void k_prep(const float* __restrict__ We, const float* __restrict__ Wn) {
    int idx = blockIdx.x * blockDim.x + threadIdx.x;
    if (idx >= 5 * H * H) return;
    int w = idx / (H * H), r = idx % (H * H);
    const float* src = (w < 3) ? (We + w * H * H) : (Wn + (w - 3) * H * H);
    float v = src[r];
    __nv_bfloat16 hi = __float2bfloat16(v);
    __nv_bfloat16 lo = __float2bfloat16(v - __bfloat162float(hi));
    g_Wimg[(size_t)w * 2 * H * H + r] = hi;
    g_Wimg[(size_t)w * 2 * H * H + H * H + r] = lo;
}

// ---- k_node_pre: zero sums; A=nf@We1+be, C=nf@We3, An=nf@Wn1+bn ----
__global__ __launch_bounds__(NT, 2)
void k_node_pre(const float* __restrict__ nf,
                const float* __restrict__ be, const float* __restrict__ bn) {
    extern __shared__ __align__(16) __nv_bfloat16 sm[];
    __nv_bfloat16* sXhi = sm;
    __nv_bfloat16* sXlo = sm + TILE_A;
    __nv_bfloat16* sWhi = sm + 2 * TILE_A;
    __nv_bfloat16* sWlo = sm + 2 * TILE_A + TILE_W;
    int t = threadIdx.x, lane = t & 31, warp = t >> 5;
    int nb = blockIdx.x * BT;

    for (int i = t; i < BT * 32; i += NT) {
        int n = nb + (i >> 5);
        if (n < NNODE) ((float4*)g_sum)[(size_t)n * 32 + (i & 31)] = make_float4(0.f, 0.f, 0.f, 0.f);
    }
    if (t < BT && nb + t < NNODE) g_cnt[nb + t] = 0.f;

    for (int i = t; i < BT * 32; i += NT) {
        int n = nb + (i >> 5);
        float4 v = make_float4(0.f, 0.f, 0.f, 0.f);
        if (n < NNODE) v = ((const float4*)nf)[(size_t)n * 32 + (i & 31)];
        split_store(sXhi, sXlo, (i >> 5) * STRIDE + (i & 31) * 4, v);
    }

    const int    wsel[3] = {0, 2, 3};
    float*       Od[3]   = {g_A, g_C, g_An};
    const float* bias[3] = {be, (const float*)0, bn};

    int rq = (lane >> 2), cb = (warp >> 2) * 64 + (lane & 3) * 2;
    int lr0 = (warp & 3) * 16 + rq, lr1 = lr0 + 8;

    for (int ph = 0; ph < 3; ph++) {
        __syncthreads();
        fill_W(sWhi, sWlo, wsel[ph], t, NT);
        __syncthreads();

        float acc[8][4];
#pragma unroll
        for (int i = 0; i < 8; i++) acc[i][0] = acc[i][1] = acc[i][2] = acc[i][3] = 0.f;
        mma_core(sXhi, sXlo, sWhi, sWlo, lane, warp, acc);

        float* O = Od[ph];
        bool w0 = (nb + lr0) < NNODE, w1 = (nb + lr1) < NNODE;
#pragma unroll
        for (int nt = 0; nt < 8; nt++) {
            int col = cb + nt * 8;
            float2 b = make_float2(0.f, 0.f);
            if (bias[ph]) b = *(const float2*)&bias[ph][col];
            if (w0) *(float2*)&O[(size_t)(nb + lr0) * H + col] =
                        make_float2(acc[nt][0] + b.x, acc[nt][1] + b.y);
            if (w1) *(float2*)&O[(size_t)(nb + lr1) * H + col] =
                        make_float2(acc[nt][2] + b.x, acc[nt][3] + b.y);
        }
    }
}

// ---- k_edge: m=ReLU(A[src]+ef@We2+C[dst]); out2=m+ef; scatter mean.
//      Staged epilogue: acc -> smem (16-row chunks) -> coalesced float4 I/O. ----
__global__ __launch_bounds__(NT, 2)
void k_edge(const float* __restrict__ ef,
            const int* __restrict__ src, const int* __restrict__ dst,
            float* __restrict__ out2) {
    extern __shared__ __align__(16) __nv_bfloat16 sm[];
    __nv_bfloat16* sXhi = sm;
    __nv_bfloat16* sXlo = sm + TILE_A;
    __nv_bfloat16* sWhi = sm + 2 * TILE_A;
    __nv_bfloat16* sWlo = sm + 2 * TILE_A + TILE_W;
    int*   s_src = (int*)(sm + 2 * TILE_A + 2 * TILE_W);     // BT ints
    int*   s_dst = s_src + BT;                               // BT ints
    float* stage = (float*)(s_dst + BT);                     // 16 x SSTRIDE f32
    int t = threadIdx.x, lane = t & 31, warp = t >> 5;

    fill_W(sWhi, sWlo, 1, t, NT);                // We2, resident for all tiles

    int rq = lane >> 2, cb = (warp >> 2) * 64 + (lane & 3) * 2;
    int wr = warp & 3;                           // acc row-group of this warp
    int lrow = t >> 4, cg = (t & 15) * 8;        // epilogue ownership

    int tiles = NTILES - blockIdx.x * TPB;
    if (tiles > TPB) tiles = TPB;

    for (int tt = 0; tt < tiles; tt++) {
        int eb = (blockIdx.x * TPB + tt) * BT;
        // (sX/stage free: trailing sync of previous tile)
        if (t < BT) s_src[t] = src[eb + t];
        else if (t < 2 * BT) s_dst[t - BT] = dst[eb + t - BT];
        const float4* ef4 = (const float4*)(ef + (size_t)eb * H);
        for (int i = t; i < BT * 32; i += NT)
            split_store(sXhi, sXlo, (i >> 5) * STRIDE + (i & 31) * 4, ef4[i]);
        __syncthreads();

        float acc[8][4];
#pragma unroll
        for (int i = 0; i < 8; i++) acc[i][0] = acc[i][1] = acc[i][2] = acc[i][3] = 0.f;
        mma_core(sXhi, sXlo, sWhi, sWlo, lane, warp, acc);

#pragma unroll
        for (int c = 0; c < 4; c++) {
            if (c) __syncthreads();              // stage free (prev chunk read)
            if (wr == c) {                       // warps c and c+4 write 16 rows
#pragma unroll
                for (int nt = 0; nt < 8; nt++) {
                    int col = cb + nt * 8;
                    *(float2*)&stage[rq * SSTRIDE + col] =
                        make_float2(acc[nt][0], acc[nt][1]);
                    *(float2*)&stage[(rq + 8) * SSTRIDE + col] =
                        make_float2(acc[nt][2], acc[nt][3]);
                }
            }
            __syncthreads();                     // stage ready

            int row = c * 16 + lrow;             // tile-local edge row
            int s = s_src[row], d = s_dst[row];
            if ((t & 15) == 0) atomicAdd(&g_cnt[d], 1.f);

            float4 st0 = *(float4*)&stage[lrow * SSTRIDE + cg];
            float4 st1 = *(float4*)&stage[lrow * SSTRIDE + cg + 4];
            float4 a0 = *(const float4*)&g_A[(size_t)s * H + cg];
            float4 a1 = *(const float4*)&g_A[(size_t)s * H + cg + 4];
            float4 c0 = *(const float4*)&g_C[(size_t)d * H + cg];
            float4 c1 = *(const float4*)&g_C[(size_t)d * H + cg + 4];
            float4 m0, m1;
            m0.x = fmaxf(st0.x + a0.x + c0.x, 0.f);
            m0.y = fmaxf(st0.y + a0.y + c0.y, 0.f);
            m0.z = fmaxf(st0.z + a0.z + c0.z, 0.f);
            m0.w = fmaxf(st0.w + a0.w + c0.w, 0.f);
            m1.x = fmaxf(st1.x + a1.x + c1.x, 0.f);
            m1.y = fmaxf(st1.y + a1.y + c1.y, 0.f);
            m1.z = fmaxf(st1.z + a1.z + c1.z, 0.f);
            m1.w = fmaxf(st1.w + a1.w + c1.w, 0.f);

            // ef reconstruct (hi+lo) from sX, row-major LDS.128
            uint4 uh = *(uint4*)&sXhi[row * STRIDE + cg];
            uint4 ul = *(uint4*)&sXlo[row * STRIDE + cg];
            const __nv_bfloat162* h2 = (const __nv_bfloat162*)&uh;
            const __nv_bfloat162* l2 = (const __nv_bfloat162*)&ul;
            float4 o0, o1;
            o0.x = (m0.x + __bfloat162float(h2[0].x)) + __bfloat162float(l2[0].x);
            o0.y = (m0.y + __bfloat162float(h2[0].y)) + __bfloat162float(l2[0].y);
            o0.z = (m0.z + __bfloat162float(h2[1].x)) + __bfloat162float(l2[1].x);
            o0.w = (m0.w + __bfloat162float(h2[1].y)) + __bfloat162float(l2[1].y);
            o1.x = (m1.x + __bfloat162float(h2[2].x)) + __bfloat162float(l2[2].x);
            o1.y = (m1.y + __bfloat162float(h2[2].y)) + __bfloat162float(l2[2].y);
            o1.z = (m1.z + __bfloat162float(h2[3].x)) + __bfloat162float(l2[3].x);
            o1.w = (m1.w + __bfloat162float(h2[3].y)) + __bfloat162float(l2[3].y);

            *(float4*)&out2[(size_t)(eb + row) * H + cg]     = o0;
            *(float4*)&out2[(size_t)(eb + row) * H + cg + 4] = o1;
            red_add_v4(&g_sum[(size_t)d * H + cg], m0);
            red_add_v4(&g_sum[(size_t)d * H + cg + 4], m1);
        }
        __syncthreads();                         // sX & stage free for next tile
    }
}

// ---- k_node_upd: out1 = ReLU(An + (sum/max(cnt,1))@Wn2) + nf ----
__global__ __launch_bounds__(NT, 2)
void k_node_upd(const float* __restrict__ nf, float* __restrict__ out1) {
    extern __shared__ __align__(16) __nv_bfloat16 sm[];
    __nv_bfloat16* sXhi = sm;
    __nv_bfloat16* sXlo = sm + TILE_A;
    __nv_bfloat16* sWhi = sm + 2 * TILE_A;
    __nv_bfloat16* sWlo = sm + 2 * TILE_A + TILE_W;
    int t = threadIdx.x, lane = t & 31, warp = t >> 5;
    int nb = blockIdx.x * BT;

    for (int i = t; i < BT * 32; i += NT) {
        int n = nb + (i >> 5);
        float4 v = make_float4(0.f, 0.f, 0.f, 0.f);
        if (n < NNODE) {
            v = ((const float4*)g_sum)[(size_t)n * 32 + (i & 31)];
            float inv = 1.0f / fmaxf(g_cnt[n], 1.0f);
            v.x *= inv; v.y *= inv; v.z *= inv; v.w *= inv;
        }
        split_store(sXhi, sXlo, (i >> 5) * STRIDE + (i & 31) * 4, v);
    }
    fill_W(sWhi, sWlo, 4, t, NT);                // Wn2
    __syncthreads();

    float acc[8][4];
#pragma unroll
    for (int i = 0; i < 8; i++) acc[i][0] = acc[i][1] = acc[i][2] = acc[i][3] = 0.f;
    mma_core(sXhi, sXlo, sWhi, sWlo, lane, warp, acc);

    int rq = lane >> 2, cb = (warp >> 2) * 64 + (lane & 3) * 2;
    int lr0 = (warp & 3) * 16 + rq, lr1 = lr0 + 8;
    bool w0 = (nb + lr0) < NNODE, w1 = (nb + lr1) < NNODE;
#pragma unroll
    for (int nt = 0; nt < 8; nt++) {
        int col = cb + nt * 8;
        if (w0) {
            float2 an = *(const float2*)&g_An[(size_t)(nb + lr0) * H + col];
            float2 nv = *(const float2*)&nf[(size_t)(nb + lr0) * H + col];
            *(float2*)&out1[(size_t)(nb + lr0) * H + col] =
                make_float2(fmaxf(acc[nt][0] + an.x, 0.f) + nv.x,
                            fmaxf(acc[nt][1] + an.y, 0.f) + nv.y);
        }
        if (w1) {
            float2 an = *(const float2*)&g_An[(size_t)(nb + lr1) * H + col];
            float2 nv = *(const float2*)&nf[(size_t)(nb + lr1) * H + col];
            *(float2*)&out1[(size_t)(nb + lr1) * H + col] =
                make_float2(fmaxf(acc[nt][2] + an.x, 0.f) + nv.x,
                            fmaxf(acc[nt][3] + an.y, 0.f) + nv.y);
        }
    }
}

extern "C" void kernel_launch(void* const* d_in, const int* in_sizes, int n_in,
                              void* d_out, int out_size) {
    const float* nf  = (const float*)d_in[0];
    const float* ef  = (const float*)d_in[1];
    const int*   src = (const int*)d_in[2];
    const int*   dst = (const int*)d_in[3];
    const float* We  = (const float*)d_in[4];
    const float* be  = (const float*)d_in[5];
    const float* Wn  = (const float*)d_in[6];
    const float* bn  = (const float*)d_in[7];
    float* out1 = (float*)d_out;                    // [N,H]
    float* out2 = out1 + (size_t)NNODE * H;         // [E,H]

    const int smem_gemm = (2 * TILE_A + 2 * TILE_W) * (int)sizeof(__nv_bfloat16); // 104448
    const int smem_edge = smem_gemm + 2 * BT * (int)sizeof(int)
                        + 16 * SSTRIDE * (int)sizeof(float);                      // 113664
    cudaFuncSetAttribute(k_node_pre, cudaFuncAttributeMaxDynamicSharedMemorySize, smem_gemm);
    cudaFuncSetAttribute(k_edge,     cudaFuncAttributeMaxDynamicSharedMemorySize, smem_edge);
    cudaFuncSetAttribute(k_node_upd, cudaFuncAttributeMaxDynamicSharedMemorySize, smem_gemm);

    k_prep<<<(5 * H * H + 255) / 256, 256>>>(We, Wn);
    k_node_pre<<<(NNODE + BT - 1) / BT, NT, smem_gemm>>>(nf, be, bn);
    k_edge<<<(NTILES + TPB - 1) / TPB, NT, smem_edge>>>(ef, src, dst, out2);
    k_node_upd<<<(NNODE + BT - 1) / BT, NT, smem_gemm>>>(nf, out1);
}

// round 9
// speedup vs baseline: 1.4622x; 1.0025x over previous
#include <cuda_runtime.h>
#include <cuda_bf16.h>
#include <cstdint>

// GCNLayer_EdgeCat on GB300 — R9:
//   * k_edge: epilogue gathers prefetched (chunk0 under MMA, chunk c+1 under
//     chunk c arithmetic) — removes exposed L2 latency per chunk.
//   * k_node_pre / k_node_upd: staged coalesced epilogues (same trick that won
//     R8 for k_edge) — g_A/g_C/g_An/out1 written as float4 row-major.
//   We=[We1;We2;We3], Wn=[Wn1;Wn2]:
//     A=nf@We1+be, C=nf@We3, An=nf@Wn1+bn        (k_node_pre)
//     m=ReLU(A[src]+ef@We2+C[dst]); out2=m+ef    (k_edge, scatter mean)
//     out1=ReLU(An+mean@Wn2)+nf                  (k_node_upd)
//   GEMMs: x=hi+lo bf16 split (AhBh+AhBl+AlBh) via mma.m16n8k16.

#define H        128
#define NNODE    50000
#define NEDGE    800000
#define BT       64           // rows per tile
#define NT       256          // 8 warps: warp = 16 rows x 64 cols
#define TPB      8            // edge tiles per block (last block: tail guard)
#define NTILES   (NEDGE / BT) // 12500
#define STRIDE   136          // bf16 row stride (272B, LDSM conflict-free)
#define SSTRIDE  136          // f32 stage stride
#define TILE_A   (BT * STRIDE)
#define TILE_W   (H * STRIDE)

__device__ float g_A  [(size_t)NNODE * H];
__device__ float g_C  [(size_t)NNODE * H];
__device__ float g_An [(size_t)NNODE * H];
__device__ float g_sum[(size_t)NNODE * H];
__device__ float g_cnt[NNODE];
// 5 weights (We1,We2,We3,Wn1,Wn2): [k][n] row-major bf16, hi image then lo image.
__device__ __nv_bfloat16 g_Wimg[5 * 2 * H * H];

// ---------- PTX helpers ----------
__device__ __forceinline__ uint32_t smem_u32(const void* p) {
    return (uint32_t)__cvta_generic_to_shared(p);
}
__device__ __forceinline__ void ldsm_x4(uint32_t a[4], uint32_t addr) {
    asm volatile("ldmatrix.sync.aligned.m8n8.x4.shared.b16 {%0,%1,%2,%3}, [%4];"
                 : "=r"(a[0]), "=r"(a[1]), "=r"(a[2]), "=r"(a[3]) : "r"(addr));
}
__device__ __forceinline__ void ldsm_x4_t(uint32_t b[4], uint32_t addr) {
    asm volatile("ldmatrix.sync.aligned.m8n8.x4.trans.shared.b16 {%0,%1,%2,%3}, [%4];"
                 : "=r"(b[0]), "=r"(b[1]), "=r"(b[2]), "=r"(b[3]) : "r"(addr));
}
__device__ __forceinline__ void mma16816(float c[4], const uint32_t a[4], const uint32_t b[2]) {
    asm volatile("mma.sync.aligned.m16n8k16.row.col.f32.bf16.bf16.f32 "
                 "{%0,%1,%2,%3}, {%4,%5,%6,%7}, {%8,%9}, {%0,%1,%2,%3};"
                 : "+f"(c[0]), "+f"(c[1]), "+f"(c[2]), "+f"(c[3])
                 : "r"(a[0]), "r"(a[1]), "r"(a[2]), "r"(a[3]), "r"(b[0]), "r"(b[1]));
}
__device__ __forceinline__ void red_add_v4(float* p, float4 v) {
    asm volatile("red.global.add.v4.f32 [%0], {%1, %2, %3, %4};"
                 :: "l"(p), "f"(v.x), "f"(v.y), "f"(v.z), "f"(v.w) : "memory");
}

// Split a float4 into hi/lo bf16 pairs and store at element offset off (even).
__device__ __forceinline__ void split_store(__nv_bfloat16* hi, __nv_bfloat16* lo,
                                            int off, float4 v) {
    __nv_bfloat16 h0 = __float2bfloat16(v.x), h1 = __float2bfloat16(v.y);
    __nv_bfloat16 h2 = __float2bfloat16(v.z), h3 = __float2bfloat16(v.w);
    __nv_bfloat16 l0 = __float2bfloat16(v.x - __bfloat162float(h0));
    __nv_bfloat16 l1 = __float2bfloat16(v.y - __bfloat162float(h1));
    __nv_bfloat16 l2 = __float2bfloat16(v.z - __bfloat162float(h2));
    __nv_bfloat16 l3 = __float2bfloat16(v.w - __bfloat162float(h3));
    *(__nv_bfloat162*)(hi + off)     = __nv_bfloat162{h0, h1};
    *(__nv_bfloat162*)(hi + off + 2) = __nv_bfloat162{h2, h3};
    *(__nv_bfloat162*)(lo + off)     = __nv_bfloat162{l0, l1};
    *(__nv_bfloat162*)(lo + off + 2) = __nv_bfloat162{l2, l3};
}

// 8-warp core: warp tile 16 rows x 64 cols.
// acc[nt][0..1]: row (warp&3)*16 + lane>>2,   col (warp>>2)*64 + nt*8 + (lane&3)*2
// acc[nt][2..3]: row +8, same cols.
__device__ __forceinline__ void mma_core(const __nv_bfloat16* sXhi, const __nv_bfloat16* sXlo,
                                         const __nv_bfloat16* sWhi, const __nv_bfloat16* sWlo,
                                         int lane, int warp, float acc[8][4]) {
    uint32_t xhi = smem_u32(sXhi), xlo = smem_u32(sXlo);
    uint32_t whi = smem_u32(sWhi), wlo = smem_u32(sWlo);
    int r0 = (warp & 3) * 16, c0 = (warp >> 2) * 64;
    uint32_t aoff = (uint32_t)((r0 + (lane & 15)) * STRIDE + ((lane >> 4) << 3)) * 2;
    uint32_t boff = (uint32_t)((lane & 15) * STRIDE + c0 + ((lane >> 4) << 3)) * 2;
#pragma unroll
    for (int k0 = 0; k0 < H; k0 += 16) {
        uint32_t ah[4], al[4];
        ldsm_x4(ah, xhi + aoff + k0 * 2);
        ldsm_x4(al, xlo + aoff + k0 * 2);
#pragma unroll
        for (int ntp = 0; ntp < 4; ntp++) {
            uint32_t bh[4], bl[4];
            uint32_t bo = boff + (uint32_t)(k0 * STRIDE + ntp * 16) * 2;
            ldsm_x4_t(bh, whi + bo);
            ldsm_x4_t(bl, wlo + bo);
            mma16816(acc[2 * ntp],     ah, bh + 0);
            mma16816(acc[2 * ntp + 1], ah, bh + 2);
            mma16816(acc[2 * ntp],     ah, bl + 0);
            mma16816(acc[2 * ntp + 1], ah, bl + 2);
            mma16816(acc[2 * ntp],     al, bh + 0);
            mma16816(acc[2 * ntp + 1], al, bh + 2);
        }
    }
}

// Stage one 16-row chunk of acc into smem (warps wr==c and wr==c+4 write).
__device__ __forceinline__ void stage_chunk(float* stage, const float acc[8][4],
                                            int c, int wr, int rq, int cb) {
    if (wr == c) {
#pragma unroll
        for (int nt = 0; nt < 8; nt++) {
            int col = cb + nt * 8;
            *(float2*)&stage[rq * SSTRIDE + col] = make_float2(acc[nt][0], acc[nt][1]);
            *(float2*)&stage[(rq + 8) * SSTRIDE + col] = make_float2(acc[nt][2], acc[nt][3]);
        }
    }
}

// Copy a prepped W image pair (hi+lo, [k][n] 128x128 bf16) into padded smem.
__device__ __forceinline__ void fill_W(__nv_bfloat16* sWhi, __nv_bfloat16* sWlo,
                                       int wsel, int t, int nthr) {
    const uint4* hi4 = (const uint4*)(g_Wimg + (size_t)wsel * 2 * H * H);
    const uint4* lo4 = hi4 + (H * H / 8);
    for (int i = t; i < H * H / 8; i += nthr) {       // 2048 uint4 per image
        int row = i >> 4, c8 = (i & 15) * 8;
        *(uint4*)(sWhi + row * STRIDE + c8) = hi4[i];
        *(uint4*)(sWlo + row * STRIDE + c8) = lo4[i];
    }
}

// ---- k_prep: split weights into bf16 hi/lo [k][n] images (once) ----
__global__ void k_prep(const float* __restrict__ We, const float* __restrict__ Wn) {
    int idx = blockIdx.x * blockDim.x + threadIdx.x;
    if (idx >= 5 * H * H) return;
    int w = idx / (H * H), r = idx % (H * H);
    const float* src = (w < 3) ? (We + w * H * H) : (Wn + (w - 3) * H * H);
    float v = src[r];
    __nv_bfloat16 hi = __float2bfloat16(v);
    __nv_bfloat16 lo = __float2bfloat16(v - __bfloat162float(hi));
    g_Wimg[(size_t)w * 2 * H * H + r] = hi;
    g_Wimg[(size_t)w * 2 * H * H + H * H + r] = lo;
}

// ---- k_node_pre: zero sums; A=nf@We1+be, C=nf@We3, An=nf@Wn1+bn (staged epi) ----
__global__ __launch_bounds__(NT, 2)
void k_node_pre(const float* __restrict__ nf,
                const float* __restrict__ be, const float* __restrict__ bn) {
    extern __shared__ __align__(16) __nv_bfloat16 sm[];
    __nv_bfloat16* sXhi = sm;
    __nv_bfloat16* sXlo = sm + TILE_A;
    __nv_bfloat16* sWhi = sm + 2 * TILE_A;
    __nv_bfloat16* sWlo = sm + 2 * TILE_A + TILE_W;
    float* stage = (float*)(sm + 2 * TILE_A + 2 * TILE_W);
    int t = threadIdx.x, lane = t & 31, warp = t >> 5;
    int nb = blockIdx.x * BT;

    for (int i = t; i < BT * 32; i += NT) {
        int n = nb + (i >> 5);
        if (n < NNODE) ((float4*)g_sum)[(size_t)n * 32 + (i & 31)] = make_float4(0.f, 0.f, 0.f, 0.f);
    }
    if (t < BT && nb + t < NNODE) g_cnt[nb + t] = 0.f;

    for (int i = t; i < BT * 32; i += NT) {
        int n = nb + (i >> 5);
        float4 v = make_float4(0.f, 0.f, 0.f, 0.f);
        if (n < NNODE) v = ((const float4*)nf)[(size_t)n * 32 + (i & 31)];
        split_store(sXhi, sXlo, (i >> 5) * STRIDE + (i & 31) * 4, v);
    }

    const int    wsel[3] = {0, 2, 3};
    float*       Od[3]   = {g_A, g_C, g_An};
    const float* bias[3] = {be, (const float*)0, bn};

    int rq = lane >> 2, cb = (warp >> 2) * 64 + (lane & 3) * 2;
    int wr = warp & 3;
    int lrow = t >> 4, cg = (t & 15) * 8;        // epilogue ownership

    for (int ph = 0; ph < 3; ph++) {
        __syncthreads();                         // prev phase epi done (sW & stage free)
        fill_W(sWhi, sWlo, wsel[ph], t, NT);
        __syncthreads();

        float acc[8][4];
#pragma unroll
        for (int i = 0; i < 8; i++) acc[i][0] = acc[i][1] = acc[i][2] = acc[i][3] = 0.f;
        mma_core(sXhi, sXlo, sWhi, sWlo, lane, warp, acc);

        float* O = Od[ph];
#pragma unroll
        for (int c = 0; c < 4; c++) {
            if (c) __syncthreads();              // stage free
            stage_chunk(stage, acc, c, wr, rq, cb);
            __syncthreads();                     // stage ready
            int n = nb + c * 16 + lrow;
            if (n < NNODE) {
                float4 st0 = *(float4*)&stage[lrow * SSTRIDE + cg];
                float4 st1 = *(float4*)&stage[lrow * SSTRIDE + cg + 4];
                float4 b0 = make_float4(0.f, 0.f, 0.f, 0.f), b1 = b0;
                if (bias[ph]) {
                    b0 = *(const float4*)&bias[ph][cg];
                    b1 = *(const float4*)&bias[ph][cg + 4];
                }
                st0.x += b0.x; st0.y += b0.y; st0.z += b0.z; st0.w += b0.w;
                st1.x += b1.x; st1.y += b1.y; st1.z += b1.z; st1.w += b1.w;
                *(float4*)&O[(size_t)n * H + cg]     = st0;
                *(float4*)&O[(size_t)n * H + cg + 4] = st1;
            }
        }
    }
}

// ---- k_edge: m=ReLU(A[src]+ef@We2+C[dst]); out2=m+ef; scatter mean.
//      Staged epilogue + gather prefetch (chunk0 under MMA, c+1 under c). ----
__global__ __launch_bounds__(NT, 2)
void k_edge(const float* __restrict__ ef,
            const int* __restrict__ src, const int* __restrict__ dst,
            float* __restrict__ out2) {
    extern __shared__ __align__(16) __nv_bfloat16 sm[];
    __nv_bfloat16* sXhi = sm;
    __nv_bfloat16* sXlo = sm + TILE_A;
    __nv_bfloat16* sWhi = sm + 2 * TILE_A;
    __nv_bfloat16* sWlo = sm + 2 * TILE_A + TILE_W;
    int*   s_src = (int*)(sm + 2 * TILE_A + 2 * TILE_W);
    int*   s_dst = s_src + BT;
    float* stage = (float*)(s_dst + BT);
    int t = threadIdx.x, lane = t & 31, warp = t >> 5;

    fill_W(sWhi, sWlo, 1, t, NT);                // We2, resident for all tiles

    int rq = lane >> 2, cb = (warp >> 2) * 64 + (lane & 3) * 2;
    int wr = warp & 3;
    int lrow = t >> 4, cg = (t & 15) * 8;

    int tiles = NTILES - blockIdx.x * TPB;
    if (tiles > TPB) tiles = TPB;

    for (int tt = 0; tt < tiles; tt++) {
        int eb = (blockIdx.x * TPB + tt) * BT;
        if (t < BT) s_src[t] = src[eb + t];
        else if (t < 2 * BT) s_dst[t - BT] = dst[eb + t - BT];
        const float4* ef4 = (const float4*)(ef + (size_t)eb * H);
        for (int i = t; i < BT * 32; i += NT)
            split_store(sXhi, sXlo, (i >> 5) * STRIDE + (i & 31) * 4, ef4[i]);
        __syncthreads();

        // prefetch chunk 0 gathers (hidden under mainloop)
        int s_p = s_src[lrow], d_p = s_dst[lrow];
        float4 pa0 = *(const float4*)&g_A[(size_t)s_p * H + cg];
        float4 pa1 = *(const float4*)&g_A[(size_t)s_p * H + cg + 4];
        float4 pc0 = *(const float4*)&g_C[(size_t)d_p * H + cg];
        float4 pc1 = *(const float4*)&g_C[(size_t)d_p * H + cg + 4];

        float acc[8][4];
#pragma unroll
        for (int i = 0; i < 8; i++) acc[i][0] = acc[i][1] = acc[i][2] = acc[i][3] = 0.f;
        mma_core(sXhi, sXlo, sWhi, sWlo, lane, warp, acc);

#pragma unroll
        for (int c = 0; c < 4; c++) {
            if (c) __syncthreads();              // stage free
            stage_chunk(stage, acc, c, wr, rq, cb);
            __syncthreads();                     // stage ready

            int row = c * 16 + lrow;
            int d = d_p;
            if ((t & 15) == 0) atomicAdd(&g_cnt[d], 1.f);

            float4 st0 = *(float4*)&stage[lrow * SSTRIDE + cg];
            float4 st1 = *(float4*)&stage[lrow * SSTRIDE + cg + 4];
            float4 m0, m1;
            m0.x = fmaxf(st0.x + pa0.x + pc0.x, 0.f);
            m0.y = fmaxf(st0.y + pa0.y + pc0.y, 0.f);
            m0.z = fmaxf(st0.z + pa0.z + pc0.z, 0.f);
            m0.w = fmaxf(st0.w + pa0.w + pc0.w, 0.f);
            m1.x = fmaxf(st1.x + pa1.x + pc1.x, 0.f);
            m1.y = fmaxf(st1.y + pa1.y + pc1.y, 0.f);
            m1.z = fmaxf(st1.z + pa1.z + pc1.z, 0.f);
            m1.w = fmaxf(st1.w + pa1.w + pc1.w, 0.f);

            // issue next chunk's gathers now (hidden under stores + barrier)
            if (c < 3) {
                int nrow = (c + 1) * 16 + lrow;
                s_p = s_src[nrow]; d_p = s_dst[nrow];
                pa0 = *(const float4*)&g_A[(size_t)s_p * H + cg];
                pa1 = *(const float4*)&g_A[(size_t)s_p * H + cg + 4];
                pc0 = *(const float4*)&g_C[(size_t)d_p * H + cg];
                pc1 = *(const float4*)&g_C[(size_t)d_p * H + cg + 4];
            }

            // ef reconstruct (hi+lo) from sX, row-major LDS.128
            uint4 uh = *(uint4*)&sXhi[row * STRIDE + cg];
            uint4 ul = *(uint4*)&sXlo[row * STRIDE + cg];
            const __nv_bfloat162* h2 = (const __nv_bfloat162*)&uh;
            const __nv_bfloat162* l2 = (const __nv_bfloat162*)&ul;
            float4 o0, o1;
            o0.x = (m0.x + __bfloat162float(h2[0].x)) + __bfloat162float(l2[0].x);
            o0.y = (m0.y + __bfloat162float(h2[0].y)) + __bfloat162float(l2[0].y);
            o0.z = (m0.z + __bfloat162float(h2[1].x)) + __bfloat162float(l2[1].x);
            o0.w = (m0.w + __bfloat162float(h2[1].y)) + __bfloat162float(l2[1].y);
            o1.x = (m1.x + __bfloat162float(h2[2].x)) + __bfloat162float(l2[2].x);
            o1.y = (m1.y + __bfloat162float(h2[2].y)) + __bfloat162float(l2[2].y);
            o1.z = (m1.z + __bfloat162float(h2[3].x)) + __bfloat162float(l2[3].x);
            o1.w = (m1.w + __bfloat162float(h2[3].y)) + __bfloat162float(l2[3].y);

            *(float4*)&out2[(size_t)(eb + row) * H + cg]     = o0;
            *(float4*)&out2[(size_t)(eb + row) * H + cg + 4] = o1;
            red_add_v4(&g_sum[(size_t)d * H + cg], m0);
            red_add_v4(&g_sum[(size_t)d * H + cg + 4], m1);
        }
        __syncthreads();                         // sX & stage free for next tile
    }
}

// ---- k_node_upd: out1 = ReLU(An + (sum/max(cnt,1))@Wn2) + nf (staged epi) ----
__global__ __launch_bounds__(NT, 2)
void k_node_upd(const float* __restrict__ nf, float* __restrict__ out1) {
    extern __shared__ __align__(16) __nv_bfloat16 sm[];
    __nv_bfloat16* sXhi = sm;
    __nv_bfloat16* sXlo = sm + TILE_A;
    __nv_bfloat16* sWhi = sm + 2 * TILE_A;
    __nv_bfloat16* sWlo = sm + 2 * TILE_A + TILE_W;
    float* stage = (float*)(sm + 2 * TILE_A + 2 * TILE_W);
    int t = threadIdx.x, lane = t & 31, warp = t >> 5;
    int nb = blockIdx.x * BT;

    for (int i = t; i < BT * 32; i += NT) {
        int n = nb + (i >> 5);
        float4 v = make_float4(0.f, 0.f, 0.f, 0.f);
        if (n < NNODE) {
            v = ((const float4*)g_sum)[(size_t)n * 32 + (i & 31)];
            float inv = 1.0f / fmaxf(g_cnt[n], 1.0f);
            v.x *= inv; v.y *= inv; v.z *= inv; v.w *= inv;
        }
        split_store(sXhi, sXlo, (i >> 5) * STRIDE + (i & 31) * 4, v);
    }
    fill_W(sWhi, sWlo, 4, t, NT);                // Wn2
    __syncthreads();

    float acc[8][4];
#pragma unroll
    for (int i = 0; i < 8; i++) acc[i][0] = acc[i][1] = acc[i][2] = acc[i][3] = 0.f;
    mma_core(sXhi, sXlo, sWhi, sWlo, lane, warp, acc);

    int rq = lane >> 2, cb = (warp >> 2) * 64 + (lane & 3) * 2;
    int wr = warp & 3;
    int lrow = t >> 4, cg = (t & 15) * 8;

#pragma unroll
    for (int c = 0; c < 4; c++) {
        if (c) __syncthreads();
        stage_chunk(stage, acc, c, wr, rq, cb);
        __syncthreads();
        int n = nb + c * 16 + lrow;
        if (n < NNODE) {
            float4 st0 = *(float4*)&stage[lrow * SSTRIDE + cg];
            float4 st1 = *(float4*)&stage[lrow * SSTRIDE + cg + 4];
            float4 an0 = *(const float4*)&g_An[(size_t)n * H + cg];
            float4 an1 = *(const float4*)&g_An[(size_t)n * H + cg + 4];
            float4 nv0 = *(const float4*)&nf[(size_t)n * H + cg];
            float4 nv1 = *(const float4*)&nf[(size_t)n * H + cg + 4];
            float4 o0, o1;
            o0.x = fmaxf(st0.x + an0.x, 0.f) + nv0.x;
            o0.y = fmaxf(st0.y + an0.y, 0.f) + nv0.y;
            o0.z = fmaxf(st0.z + an0.z, 0.f) + nv0.z;
            o0.w = fmaxf(st0.w + an0.w, 0.f) + nv0.w;
            o1.x = fmaxf(st1.x + an1.x, 0.f) + nv1.x;
            o1.y = fmaxf(st1.y + an1.y, 0.f) + nv1.y;
            o1.z = fmaxf(st1.z + an1.z, 0.f) + nv1.z;
            o1.w = fmaxf(st1.w + an1.w, 0.f) + nv1.w;
            *(float4*)&out1[(size_t)n * H + cg]     = o0;
            *(float4*)&out1[(size_t)n * H + cg + 4] = o1;
        }
    }
}

extern "C" void kernel_launch(void* const* d_in, const int* in_sizes, int n_in,
                              void* d_out, int out_size) {
    const float* nf  = (const float*)d_in[0];
    const float* ef  = (const float*)d_in[1];
    const int*   src = (const int*)d_in[2];
    const int*   dst = (const int*)d_in[3];
    const float* We  = (const float*)d_in[4];
    const float* be  = (const float*)d_in[5];
    const float* Wn  = (const float*)d_in[6];
    const float* bn  = (const float*)d_in[7];
    float* out1 = (float*)d_out;                    // [N,H]
    float* out2 = out1 + (size_t)NNODE * H;         // [E,H]

    const int smem_gemm = (2 * TILE_A + 2 * TILE_W) * (int)sizeof(__nv_bfloat16); // 104448
    const int smem_node = smem_gemm + 16 * SSTRIDE * (int)sizeof(float);          // 113152
    const int smem_edge = smem_gemm + 2 * BT * (int)sizeof(int)
                        + 16 * SSTRIDE * (int)sizeof(float);                      // 113664
    cudaFuncSetAttribute(k_node_pre, cudaFuncAttributeMaxDynamicSharedMemorySize, smem_node);
    cudaFuncSetAttribute(k_edge,     cudaFuncAttributeMaxDynamicSharedMemorySize, smem_edge);
    cudaFuncSetAttribute(k_node_upd, cudaFuncAttributeMaxDynamicSharedMemorySize, smem_node);

    k_prep<<<(5 * H * H + 255) / 256, 256>>>(We, Wn);
    k_node_pre<<<(NNODE + BT - 1) / BT, NT, smem_node>>>(nf, be, bn);
    k_edge<<<(NTILES + TPB - 1) / TPB, NT, smem_edge>>>(ef, src, dst, out2);
    k_node_upd<<<(NNODE + BT - 1) / BT, NT, smem_node>>>(nf, out1);
}

// round 10
// speedup vs baseline: 1.6962x; 1.1600x over previous
#include <cuda_runtime.h>
#include <cuda_fp16.h>
#include <cstdint>

// GCNLayer_EdgeCat on GB300 — R10: fp16 2-term split (A=ah+al fp16, W single
// fp16) => 128 MMAs/warp-tile (was 192), half the W smem/LDSM; ping-pong acc
// stage halves barrier count. Predicted rel_err ~1.5e-4 (validated RMS model).
//   We=[We1;We2;We3], Wn=[Wn1;Wn2]:
//     A=nf@We1+be, C=nf@We3, An=nf@Wn1+bn        (k_node_pre)
//     m=ReLU(A[src]+ef@We2+C[dst]); out2=m+ef    (k_edge, scatter mean)
//     out1=ReLU(An+mean@Wn2)+nf                  (k_node_upd)

#define H        128
#define NNODE    50000
#define NEDGE    800000
#define BT       64           // rows per tile
#define NT       256          // 8 warps: warp = 16 rows x 64 cols
#define TPB      8            // edge tiles per block (last block: tail guard)
#define NTILES   (NEDGE / BT) // 12500
#define STRIDE   136          // fp16 row stride (272B, LDSM conflict-free)
#define SSTRIDE  136          // f32 stage stride
#define TILE_A   (BT * STRIDE)
#define TILE_W   (H * STRIDE)

__device__ float g_A  [(size_t)NNODE * H];
__device__ float g_C  [(size_t)NNODE * H];
__device__ float g_An [(size_t)NNODE * H];
__device__ float g_sum[(size_t)NNODE * H];
__device__ float g_cnt[NNODE];
// 5 weights (We1,We2,We3,Wn1,Wn2): [k][n] row-major fp16 (single image).
__device__ __half g_Wimg[5 * H * H];

// ---------- PTX helpers ----------
__device__ __forceinline__ uint32_t smem_u32(const void* p) {
    return (uint32_t)__cvta_generic_to_shared(p);
}
__device__ __forceinline__ void ldsm_x4(uint32_t a[4], uint32_t addr) {
    asm volatile("ldmatrix.sync.aligned.m8n8.x4.shared.b16 {%0,%1,%2,%3}, [%4];"
                 : "=r"(a[0]), "=r"(a[1]), "=r"(a[2]), "=r"(a[3]) : "r"(addr));
}
__device__ __forceinline__ void ldsm_x4_t(uint32_t b[4], uint32_t addr) {
    asm volatile("ldmatrix.sync.aligned.m8n8.x4.trans.shared.b16 {%0,%1,%2,%3}, [%4];"
                 : "=r"(b[0]), "=r"(b[1]), "=r"(b[2]), "=r"(b[3]) : "r"(addr));
}
__device__ __forceinline__ void mma16816(float c[4], const uint32_t a[4], const uint32_t b[2]) {
    asm volatile("mma.sync.aligned.m16n8k16.row.col.f32.f16.f16.f32 "
                 "{%0,%1,%2,%3}, {%4,%5,%6,%7}, {%8,%9}, {%0,%1,%2,%3};"
                 : "+f"(c[0]), "+f"(c[1]), "+f"(c[2]), "+f"(c[3])
                 : "r"(a[0]), "r"(a[1]), "r"(a[2]), "r"(a[3]), "r"(b[0]), "r"(b[1]));
}
__device__ __forceinline__ void red_add_v4(float* p, float4 v) {
    asm volatile("red.global.add.v4.f32 [%0], {%1, %2, %3, %4};"
                 :: "l"(p), "f"(v.x), "f"(v.y), "f"(v.z), "f"(v.w) : "memory");
}

// Split a float4 into fp16 hi/lo pairs and store at element offset off (even).
__device__ __forceinline__ void split_store(__half* hi, __half* lo, int off, float4 v) {
    __half h0 = __float2half_rn(v.x), h1 = __float2half_rn(v.y);
    __half h2 = __float2half_rn(v.z), h3 = __float2half_rn(v.w);
    __half l0 = __float2half_rn(v.x - __half2float(h0));
    __half l1 = __float2half_rn(v.y - __half2float(h1));
    __half l2 = __float2half_rn(v.z - __half2float(h2));
    __half l3 = __float2half_rn(v.w - __half2float(h3));
    *(__half2*)(hi + off)     = __half2{h0, h1};
    *(__half2*)(hi + off + 2) = __half2{h2, h3};
    *(__half2*)(lo + off)     = __half2{l0, l1};
    *(__half2*)(lo + off + 2) = __half2{l2, l3};
}

// 8-warp core: warp tile 16 rows x 64 cols. 2-term: acc += ah*B + al*B.
// acc[nt][0..1]: row (warp&3)*16 + lane>>2,   col (warp>>2)*64 + nt*8 + (lane&3)*2
// acc[nt][2..3]: row +8, same cols.
__device__ __forceinline__ void mma_core(const __half* sXhi, const __half* sXlo,
                                         const __half* sW,
                                         int lane, int warp, float acc[8][4]) {
    uint32_t xhi = smem_u32(sXhi), xlo = smem_u32(sXlo);
    uint32_t w = smem_u32(sW);
    int r0 = (warp & 3) * 16, c0 = (warp >> 2) * 64;
    uint32_t aoff = (uint32_t)((r0 + (lane & 15)) * STRIDE + ((lane >> 4) << 3)) * 2;
    uint32_t boff = (uint32_t)((lane & 15) * STRIDE + c0 + ((lane >> 4) << 3)) * 2;
#pragma unroll
    for (int k0 = 0; k0 < H; k0 += 16) {
        uint32_t ah[4], al[4];
        ldsm_x4(ah, xhi + aoff + k0 * 2);
        ldsm_x4(al, xlo + aoff + k0 * 2);
#pragma unroll
        for (int ntp = 0; ntp < 4; ntp++) {
            uint32_t b[4];
            ldsm_x4_t(b, w + boff + (uint32_t)(k0 * STRIDE + ntp * 16) * 2);
            mma16816(acc[2 * ntp],     ah, b + 0);
            mma16816(acc[2 * ntp + 1], ah, b + 2);
            mma16816(acc[2 * ntp],     al, b + 0);
            mma16816(acc[2 * ntp + 1], al, b + 2);
        }
    }
}

// Stage one 16-row chunk of acc into smem (warps wr==c and wr==c+4 write).
__device__ __forceinline__ void stage_chunk(float* stg, const float acc[8][4],
                                            int c, int wr, int rq, int cb) {
    if (wr == c) {
#pragma unroll
        for (int nt = 0; nt < 8; nt++) {
            int col = cb + nt * 8;
            *(float2*)&stg[rq * SSTRIDE + col] = make_float2(acc[nt][0], acc[nt][1]);
            *(float2*)&stg[(rq + 8) * SSTRIDE + col] = make_float2(acc[nt][2], acc[nt][3]);
        }
    }
}

// Copy a prepped W image ([k][n] 128x128 fp16) into padded smem.
__device__ __forceinline__ void fill_W(__half* sW, int wsel, int t, int nthr) {
    const uint4* w4 = (const uint4*)(g_Wimg + (size_t)wsel * H * H);
    for (int i = t; i < H * H / 8; i += nthr) {       // 2048 uint4
        int row = i >> 4, c8 = (i & 15) * 8;
        *(uint4*)(sW + row * STRIDE + c8) = w4[i];
    }
}

// ---- k_prep: weights -> fp16 [k][n] images (once) ----
__global__ void k_prep(const float* __restrict__ We, const float* __restrict__ Wn) {
    int idx = blockIdx.x * blockDim.x + threadIdx.x;
    if (idx >= 5 * H * H) return;
    int w = idx / (H * H), r = idx % (H * H);
    const float* src = (w < 3) ? (We + w * H * H) : (Wn + (w - 3) * H * H);
    g_Wimg[(size_t)w * H * H + r] = __float2half_rn(src[r]);
}

// ---- k_node_pre: zero sums; A=nf@We1+be, C=nf@We3, An=nf@Wn1+bn ----
__global__ __launch_bounds__(NT, 2)
void k_node_pre(const float* __restrict__ nf,
                const float* __restrict__ be, const float* __restrict__ bn) {
    extern __shared__ __align__(16) __half sm[];
    __half* sXhi = sm;
    __half* sXlo = sm + TILE_A;
    __half* sW   = sm + 2 * TILE_A;
    float* stage = (float*)(sm + 2 * TILE_A + TILE_W);   // 2 x 16 x SSTRIDE
    int t = threadIdx.x, lane = t & 31, warp = t >> 5;
    int nb = blockIdx.x * BT;

    for (int i = t; i < BT * 32; i += NT) {
        int n = nb + (i >> 5);
        if (n < NNODE) ((float4*)g_sum)[(size_t)n * 32 + (i & 31)] = make_float4(0.f, 0.f, 0.f, 0.f);
    }
    if (t < BT && nb + t < NNODE) g_cnt[nb + t] = 0.f;

    for (int i = t; i < BT * 32; i += NT) {
        int n = nb + (i >> 5);
        float4 v = make_float4(0.f, 0.f, 0.f, 0.f);
        if (n < NNODE) v = ((const float4*)nf)[(size_t)n * 32 + (i & 31)];
        split_store(sXhi, sXlo, (i >> 5) * STRIDE + (i & 31) * 4, v);
    }

    const int    wsel[3] = {0, 2, 3};
    float*       Od[3]   = {g_A, g_C, g_An};
    const float* bias[3] = {be, (const float*)0, bn};

    int rq = lane >> 2, cb = (warp >> 2) * 64 + (lane & 3) * 2;
    int wr = warp & 3;
    int lrow = t >> 4, cg = (t & 15) * 8;        // epilogue ownership

    for (int ph = 0; ph < 3; ph++) {
        __syncthreads();                         // prev phase fully consumed
        fill_W(sW, wsel[ph], t, NT);
        __syncthreads();

        float acc[8][4];
#pragma unroll
        for (int i = 0; i < 8; i++) acc[i][0] = acc[i][1] = acc[i][2] = acc[i][3] = 0.f;
        mma_core(sXhi, sXlo, sW, lane, warp, acc);

        float* O = Od[ph];
#pragma unroll
        for (int c = 0; c < 4; c++) {
            float* stg = stage + (c & 1) * (16 * SSTRIDE);
            stage_chunk(stg, acc, c, wr, rq, cb);
            __syncthreads();                     // stage(c) ready
            int n = nb + c * 16 + lrow;
            if (n < NNODE) {
                float4 st0 = *(float4*)&stg[lrow * SSTRIDE + cg];
                float4 st1 = *(float4*)&stg[lrow * SSTRIDE + cg + 4];
                if (bias[ph]) {
                    float4 b0 = *(const float4*)&bias[ph][cg];
                    float4 b1 = *(const float4*)&bias[ph][cg + 4];
                    st0.x += b0.x; st0.y += b0.y; st0.z += b0.z; st0.w += b0.w;
                    st1.x += b1.x; st1.y += b1.y; st1.z += b1.z; st1.w += b1.w;
                }
                *(float4*)&O[(size_t)n * H + cg]     = st0;
                *(float4*)&O[(size_t)n * H + cg + 4] = st1;
            }
        }
    }
}

// ---- k_edge: m=ReLU(A[src]+ef@We2+C[dst]); out2=m+ef; scatter mean ----
__global__ __launch_bounds__(NT, 2)
void k_edge(const float* __restrict__ ef,
            const int* __restrict__ src, const int* __restrict__ dst,
            float* __restrict__ out2) {
    extern __shared__ __align__(16) __half sm[];
    __half* sXhi = sm;
    __half* sXlo = sm + TILE_A;
    __half* sW   = sm + 2 * TILE_A;
    int*   s_src = (int*)(sm + 2 * TILE_A + TILE_W);
    int*   s_dst = s_src + BT;
    float* stage = (float*)(s_dst + BT);                 // 2 x 16 x SSTRIDE
    int t = threadIdx.x, lane = t & 31, warp = t >> 5;

    fill_W(sW, 1, t, NT);                        // We2, resident for all tiles

    int rq = lane >> 2, cb = (warp >> 2) * 64 + (lane & 3) * 2;
    int wr = warp & 3;
    int lrow = t >> 4, cg = (t & 15) * 8;

    int tiles = NTILES - blockIdx.x * TPB;
    if (tiles > TPB) tiles = TPB;

    for (int tt = 0; tt < tiles; tt++) {
        int eb = (blockIdx.x * TPB + tt) * BT;
        if (t < BT) s_src[t] = src[eb + t];
        else if (t < 2 * BT) s_dst[t - BT] = dst[eb + t - BT];
        const float4* ef4 = (const float4*)(ef + (size_t)eb * H);
        for (int i = t; i < BT * 32; i += NT)
            split_store(sXhi, sXlo, (i >> 5) * STRIDE + (i & 31) * 4, ef4[i]);
        __syncthreads();

        // prefetch chunk 0 gathers (hidden under mainloop)
        int s_p = s_src[lrow], d_p = s_dst[lrow];
        float4 pa0 = *(const float4*)&g_A[(size_t)s_p * H + cg];
        float4 pa1 = *(const float4*)&g_A[(size_t)s_p * H + cg + 4];
        float4 pc0 = *(const float4*)&g_C[(size_t)d_p * H + cg];
        float4 pc1 = *(const float4*)&g_C[(size_t)d_p * H + cg + 4];

        float acc[8][4];
#pragma unroll
        for (int i = 0; i < 8; i++) acc[i][0] = acc[i][1] = acc[i][2] = acc[i][3] = 0.f;
        mma_core(sXhi, sXlo, sW, lane, warp, acc);

#pragma unroll
        for (int c = 0; c < 4; c++) {
            float* stg = stage + (c & 1) * (16 * SSTRIDE);
            stage_chunk(stg, acc, c, wr, rq, cb);
            __syncthreads();                     // stage(c) ready

            int row = c * 16 + lrow;
            int d = d_p;
            if ((t & 15) == 0) atomicAdd(&g_cnt[d], 1.f);

            float4 st0 = *(float4*)&stg[lrow * SSTRIDE + cg];
            float4 st1 = *(float4*)&stg[lrow * SSTRIDE + cg + 4];
            float4 m0, m1;
            m0.x = fmaxf(st0.x + pa0.x + pc0.x, 0.f);
            m0.y = fmaxf(st0.y + pa0.y + pc0.y, 0.f);
            m0.z = fmaxf(st0.z + pa0.z + pc0.z, 0.f);
            m0.w = fmaxf(st0.w + pa0.w + pc0.w, 0.f);
            m1.x = fmaxf(st1.x + pa1.x + pc1.x, 0.f);
            m1.y = fmaxf(st1.y + pa1.y + pc1.y, 0.f);
            m1.z = fmaxf(st1.z + pa1.z + pc1.z, 0.f);
            m1.w = fmaxf(st1.w + pa1.w + pc1.w, 0.f);

            if (c < 3) {                         // next chunk's gathers
                int nrow = (c + 1) * 16 + lrow;
                s_p = s_src[nrow]; d_p = s_dst[nrow];
                pa0 = *(const float4*)&g_A[(size_t)s_p * H + cg];
                pa1 = *(const float4*)&g_A[(size_t)s_p * H + cg + 4];
                pc0 = *(const float4*)&g_C[(size_t)d_p * H + cg];
                pc1 = *(const float4*)&g_C[(size_t)d_p * H + cg + 4];
            }

            // ef reconstruct (hi+lo) from sX, row-major LDS.128
            uint4 uh = *(uint4*)&sXhi[row * STRIDE + cg];
            uint4 ul = *(uint4*)&sXlo[row * STRIDE + cg];
            const __half2* h2 = (const __half2*)&uh;
            const __half2* l2 = (const __half2*)&ul;
            float4 o0, o1;
            o0.x = (m0.x + __half2float(h2[0].x)) + __half2float(l2[0].x);
            o0.y = (m0.y + __half2float(h2[0].y)) + __half2float(l2[0].y);
            o0.z = (m0.z + __half2float(h2[1].x)) + __half2float(l2[1].x);
            o0.w = (m0.w + __half2float(h2[1].y)) + __half2float(l2[1].y);
            o1.x = (m1.x + __half2float(h2[2].x)) + __half2float(l2[2].x);
            o1.y = (m1.y + __half2float(h2[2].y)) + __half2float(l2[2].y);
            o1.z = (m1.z + __half2float(h2[3].x)) + __half2float(l2[3].x);
            o1.w = (m1.w + __half2float(h2[3].y)) + __half2float(l2[3].y);

            *(float4*)&out2[(size_t)(eb + row) * H + cg]     = o0;
            *(float4*)&out2[(size_t)(eb + row) * H + cg + 4] = o1;
            red_add_v4(&g_sum[(size_t)d * H + cg], m0);
            red_add_v4(&g_sum[(size_t)d * H + cg + 4], m1);
        }
        __syncthreads();                         // sX & stage free for next tile
    }
}

// ---- k_node_upd: out1 = ReLU(An + (sum/max(cnt,1))@Wn2) + nf ----
__global__ __launch_bounds__(NT, 2)
void k_node_upd(const float* __restrict__ nf, float* __restrict__ out1) {
    extern __shared__ __align__(16) __half sm[];
    __half* sXhi = sm;
    __half* sXlo = sm + TILE_A;
    __half* sW   = sm + 2 * TILE_A;
    float* stage = (float*)(sm + 2 * TILE_A + TILE_W);
    int t = threadIdx.x, lane = t & 31, warp = t >> 5;
    int nb = blockIdx.x * BT;

    for (int i = t; i < BT * 32; i += NT) {
        int n = nb + (i >> 5);
        float4 v = make_float4(0.f, 0.f, 0.f, 0.f);
        if (n < NNODE) {
            v = ((const float4*)g_sum)[(size_t)n * 32 + (i & 31)];
            float inv = 1.0f / fmaxf(g_cnt[n], 1.0f);
            v.x *= inv; v.y *= inv; v.z *= inv; v.w *= inv;
        }
        split_store(sXhi, sXlo, (i >> 5) * STRIDE + (i & 31) * 4, v);
    }
    fill_W(sW, 4, t, NT);                        // Wn2
    __syncthreads();

    float acc[8][4];
#pragma unroll
    for (int i = 0; i < 8; i++) acc[i][0] = acc[i][1] = acc[i][2] = acc[i][3] = 0.f;
    mma_core(sXhi, sXlo, sW, lane, warp, acc);

    int rq = lane >> 2, cb = (warp >> 2) * 64 + (lane & 3) * 2;
    int wr = warp & 3;
    int lrow = t >> 4, cg = (t & 15) * 8;

#pragma unroll
    for (int c = 0; c < 4; c++) {
        float* stg = stage + (c & 1) * (16 * SSTRIDE);
        stage_chunk(stg, acc, c, wr, rq, cb);
        __syncthreads();
        int n = nb + c * 16 + lrow;
        if (n < NNODE) {
            float4 st0 = *(float4*)&stg[lrow * SSTRIDE + cg];
            float4 st1 = *(float4*)&stg[lrow * SSTRIDE + cg + 4];
            float4 an0 = *(const float4*)&g_An[(size_t)n * H + cg];
            float4 an1 = *(const float4*)&g_An[(size_t)n * H + cg + 4];
            float4 nv0 = *(const float4*)&nf[(size_t)n * H + cg];
            float4 nv1 = *(const float4*)&nf[(size_t)n * H + cg + 4];
            float4 o0, o1;
            o0.x = fmaxf(st0.x + an0.x, 0.f) + nv0.x;
            o0.y = fmaxf(st0.y + an0.y, 0.f) + nv0.y;
            o0.z = fmaxf(st0.z + an0.z, 0.f) + nv0.z;
            o0.w = fmaxf(st0.w + an0.w, 0.f) + nv0.w;
            o1.x = fmaxf(st1.x + an1.x, 0.f) + nv1.x;
            o1.y = fmaxf(st1.y + an1.y, 0.f) + nv1.y;
            o1.z = fmaxf(st1.z + an1.z, 0.f) + nv1.z;
            o1.w = fmaxf(st1.w + an1.w, 0.f) + nv1.w;
            *(float4*)&out1[(size_t)n * H + cg]     = o0;
            *(float4*)&out1[(size_t)n * H + cg + 4] = o1;
        }
    }
}

extern "C" void kernel_launch(void* const* d_in, const int* in_sizes, int n_in,
                              void* d_out, int out_size) {
    const float* nf  = (const float*)d_in[0];
    const float* ef  = (const float*)d_in[1];
    const int*   src = (const int*)d_in[2];
    const int*   dst = (const int*)d_in[3];
    const float* We  = (const float*)d_in[4];
    const float* be  = (const float*)d_in[5];
    const float* Wn  = (const float*)d_in[6];
    const float* bn  = (const float*)d_in[7];
    float* out1 = (float*)d_out;                    // [N,H]
    float* out2 = out1 + (size_t)NNODE * H;         // [E,H]

    const int smem_gemm = (2 * TILE_A + TILE_W) * (int)sizeof(__half);        // 69632
    const int smem_node = smem_gemm + 2 * 16 * SSTRIDE * (int)sizeof(float);  // 87040
    const int smem_edge = smem_gemm + 2 * BT * (int)sizeof(int)
                        + 2 * 16 * SSTRIDE * (int)sizeof(float);              // 87552
    cudaFuncSetAttribute(k_node_pre, cudaFuncAttributeMaxDynamicSharedMemorySize, smem_node);
    cudaFuncSetAttribute(k_edge,     cudaFuncAttributeMaxDynamicSharedMemorySize, smem_edge);
    cudaFuncSetAttribute(k_node_upd, cudaFuncAttributeMaxDynamicSharedMemorySize, smem_node);

    k_prep<<<(5 * H * H + 255) / 256, 256>>>(We, Wn);
    k_node_pre<<<(NNODE + BT - 1) / BT, NT, smem_node>>>(nf, be, bn);
    k_edge<<<(NTILES + TPB - 1) / TPB, NT, smem_edge>>>(ef, src, dst, out2);
    k_node_upd<<<(NNODE + BT - 1) / BT, NT, smem_node>>>(nf, out1);
}

// round 11
// speedup vs baseline: 1.7910x; 1.0559x over previous
#include <cuda_runtime.h>
#include <cuda_fp16.h>
#include <cstdint>

// GCNLayer_EdgeCat on GB300 — R11: single-fp16 MMA (A hi-only, W fp16) =>
// 64 MMAs/warp-tile (was 128). Calibrated error model: W-fp16 alone measured
// 1.2e-4; A-fp16 adds in quadrature => ~2e-4 predicted (gate 1e-3).
// k_edge still stores ef hi+lo in smem so out2 = m + ef keeps fp32-accurate ef.
//   We=[We1;We2;We3], Wn=[Wn1;Wn2]:
//     A=nf@We1+be, C=nf@We3, An=nf@Wn1+bn        (k_node_pre)
//     m=ReLU(A[src]+ef@We2+C[dst]); out2=m+ef    (k_edge, scatter mean)
//     out1=ReLU(An+mean@Wn2)+nf                  (k_node_upd)

#define H        128
#define NNODE    50000
#define NEDGE    800000
#define BT       64           // rows per tile
#define NT       256          // 8 warps: warp = 16 rows x 64 cols
#define TPB      8            // edge tiles per block (last block: tail guard)
#define NTILES   (NEDGE / BT) // 12500
#define STRIDE   136          // fp16 row stride (272B, LDSM conflict-free)
#define SSTRIDE  136          // f32 stage stride
#define TILE_A   (BT * STRIDE)
#define TILE_W   (H * STRIDE)

__device__ float g_A  [(size_t)NNODE * H];
__device__ float g_C  [(size_t)NNODE * H];
__device__ float g_An [(size_t)NNODE * H];
__device__ float g_sum[(size_t)NNODE * H];
__device__ float g_cnt[NNODE];
// 5 weights (We1,We2,We3,Wn1,Wn2): [k][n] row-major fp16.
__device__ __half g_Wimg[5 * H * H];

// ---------- PTX helpers ----------
__device__ __forceinline__ uint32_t smem_u32(const void* p) {
    return (uint32_t)__cvta_generic_to_shared(p);
}
__device__ __forceinline__ void ldsm_x4(uint32_t a[4], uint32_t addr) {
    asm volatile("ldmatrix.sync.aligned.m8n8.x4.shared.b16 {%0,%1,%2,%3}, [%4];"
                 : "=r"(a[0]), "=r"(a[1]), "=r"(a[2]), "=r"(a[3]) : "r"(addr));
}
__device__ __forceinline__ void ldsm_x4_t(uint32_t b[4], uint32_t addr) {
    asm volatile("ldmatrix.sync.aligned.m8n8.x4.trans.shared.b16 {%0,%1,%2,%3}, [%4];"
                 : "=r"(b[0]), "=r"(b[1]), "=r"(b[2]), "=r"(b[3]) : "r"(addr));
}
__device__ __forceinline__ void mma16816(float c[4], const uint32_t a[4], const uint32_t b[2]) {
    asm volatile("mma.sync.aligned.m16n8k16.row.col.f32.f16.f16.f32 "
                 "{%0,%1,%2,%3}, {%4,%5,%6,%7}, {%8,%9}, {%0,%1,%2,%3};"
                 : "+f"(c[0]), "+f"(c[1]), "+f"(c[2]), "+f"(c[3])
                 : "r"(a[0]), "r"(a[1]), "r"(a[2]), "r"(a[3]), "r"(b[0]), "r"(b[1]));
}
__device__ __forceinline__ void red_add_v4(float* p, float4 v) {
    asm volatile("red.global.add.v4.f32 [%0], {%1, %2, %3, %4};"
                 :: "l"(p), "f"(v.x), "f"(v.y), "f"(v.z), "f"(v.w) : "memory");
}

// Store a float4 as 4 fp16 at element offset off (hi image only).
__device__ __forceinline__ void store_hi(__half* hi, int off, float4 v) {
    *(__half2*)(hi + off)     = __half2{__float2half_rn(v.x), __float2half_rn(v.y)};
    *(__half2*)(hi + off + 2) = __half2{__float2half_rn(v.z), __float2half_rn(v.w)};
}
// Store hi + residual lo (k_edge only: lo used for exact ef reconstruction).
__device__ __forceinline__ void split_store(__half* hi, __half* lo, int off, float4 v) {
    __half h0 = __float2half_rn(v.x), h1 = __float2half_rn(v.y);
    __half h2 = __float2half_rn(v.z), h3 = __float2half_rn(v.w);
    *(__half2*)(hi + off)     = __half2{h0, h1};
    *(__half2*)(hi + off + 2) = __half2{h2, h3};
    *(__half2*)(lo + off)     = __half2{__float2half_rn(v.x - __half2float(h0)),
                                        __float2half_rn(v.y - __half2float(h1))};
    *(__half2*)(lo + off + 2) = __half2{__float2half_rn(v.z - __half2float(h2)),
                                        __float2half_rn(v.w - __half2float(h3))};
}

// 8-warp core: warp tile 16 rows x 64 cols, single-term fp16 (64 MMAs).
// acc[nt][0..1]: row (warp&3)*16 + lane>>2,   col (warp>>2)*64 + nt*8 + (lane&3)*2
// acc[nt][2..3]: row +8, same cols.
__device__ __forceinline__ void mma_core(const __half* sX, const __half* sW,
                                         int lane, int warp, float acc[8][4]) {
    uint32_t x = smem_u32(sX), w = smem_u32(sW);
    int r0 = (warp & 3) * 16, c0 = (warp >> 2) * 64;
    uint32_t aoff = (uint32_t)((r0 + (lane & 15)) * STRIDE + ((lane >> 4) << 3)) * 2;
    uint32_t boff = (uint32_t)((lane & 15) * STRIDE + c0 + ((lane >> 4) << 3)) * 2;
#pragma unroll
    for (int k0 = 0; k0 < H; k0 += 16) {
        uint32_t a[4];
        ldsm_x4(a, x + aoff + k0 * 2);
#pragma unroll
        for (int ntp = 0; ntp < 4; ntp++) {
            uint32_t b[4];
            ldsm_x4_t(b, w + boff + (uint32_t)(k0 * STRIDE + ntp * 16) * 2);
            mma16816(acc[2 * ntp],     a, b + 0);
            mma16816(acc[2 * ntp + 1], a, b + 2);
        }
    }
}

// Stage one 16-row chunk of acc into smem (warps wr==c and wr==c+4 write).
__device__ __forceinline__ void stage_chunk(float* stg, const float acc[8][4],
                                            int c, int wr, int rq, int cb) {
    if (wr == c) {
#pragma unroll
        for (int nt = 0; nt < 8; nt++) {
            int col = cb + nt * 8;
            *(float2*)&stg[rq * SSTRIDE + col] = make_float2(acc[nt][0], acc[nt][1]);
            *(float2*)&stg[(rq + 8) * SSTRIDE + col] = make_float2(acc[nt][2], acc[nt][3]);
        }
    }
}

// Copy a prepped W image ([k][n] 128x128 fp16) into padded smem.
__device__ __forceinline__ void fill_W(__half* sW, int wsel, int t, int nthr) {
    const uint4* w4 = (const uint4*)(g_Wimg + (size_t)wsel * H * H);
    for (int i = t; i < H * H / 8; i += nthr) {       // 2048 uint4
        int row = i >> 4, c8 = (i & 15) * 8;
        *(uint4*)(sW + row * STRIDE + c8) = w4[i];
    }
}

// ---- k_prep: weights -> fp16 [k][n] images (once) ----
__global__ void k_prep(const float* __restrict__ We, const float* __restrict__ Wn) {
    int idx = blockIdx.x * blockDim.x + threadIdx.x;
    if (idx >= 5 * H * H) return;
    int w = idx / (H * H), r = idx % (H * H);
    const float* src = (w < 3) ? (We + w * H * H) : (Wn + (w - 3) * H * H);
    g_Wimg[(size_t)w * H * H + r] = __float2half_rn(src[r]);
}

// ---- k_node_pre: zero sums; A=nf@We1+be, C=nf@We3, An=nf@Wn1+bn ----
__global__ __launch_bounds__(NT, 2)
void k_node_pre(const float* __restrict__ nf,
                const float* __restrict__ be, const float* __restrict__ bn) {
    extern __shared__ __align__(16) __half sm[];
    __half* sX = sm;
    __half* sW = sm + TILE_A;
    float* stage = (float*)(sm + TILE_A + TILE_W);   // 2 x 16 x SSTRIDE
    int t = threadIdx.x, lane = t & 31, warp = t >> 5;
    int nb = blockIdx.x * BT;

    for (int i = t; i < BT * 32; i += NT) {
        int n = nb + (i >> 5);
        if (n < NNODE) ((float4*)g_sum)[(size_t)n * 32 + (i & 31)] = make_float4(0.f, 0.f, 0.f, 0.f);
    }
    if (t < BT && nb + t < NNODE) g_cnt[nb + t] = 0.f;

    for (int i = t; i < BT * 32; i += NT) {
        int n = nb + (i >> 5);
        float4 v = make_float4(0.f, 0.f, 0.f, 0.f);
        if (n < NNODE) v = ((const float4*)nf)[(size_t)n * 32 + (i & 31)];
        store_hi(sX, (i >> 5) * STRIDE + (i & 31) * 4, v);
    }

    const int    wsel[3] = {0, 2, 3};
    float*       Od[3]   = {g_A, g_C, g_An};
    const float* bias[3] = {be, (const float*)0, bn};

    int rq = lane >> 2, cb = (warp >> 2) * 64 + (lane & 3) * 2;
    int wr = warp & 3;
    int lrow = t >> 4, cg = (t & 15) * 8;        // epilogue ownership

    for (int ph = 0; ph < 3; ph++) {
        __syncthreads();                         // prev phase fully consumed
        fill_W(sW, wsel[ph], t, NT);
        __syncthreads();

        float acc[8][4];
#pragma unroll
        for (int i = 0; i < 8; i++) acc[i][0] = acc[i][1] = acc[i][2] = acc[i][3] = 0.f;
        mma_core(sX, sW, lane, warp, acc);

        float* O = Od[ph];
#pragma unroll
        for (int c = 0; c < 4; c++) {
            float* stg = stage + (c & 1) * (16 * SSTRIDE);
            stage_chunk(stg, acc, c, wr, rq, cb);
            __syncthreads();                     // stage(c) ready
            int n = nb + c * 16 + lrow;
            if (n < NNODE) {
                float4 st0 = *(float4*)&stg[lrow * SSTRIDE + cg];
                float4 st1 = *(float4*)&stg[lrow * SSTRIDE + cg + 4];
                if (bias[ph]) {
                    float4 b0 = *(const float4*)&bias[ph][cg];
                    float4 b1 = *(const float4*)&bias[ph][cg + 4];
                    st0.x += b0.x; st0.y += b0.y; st0.z += b0.z; st0.w += b0.w;
                    st1.x += b1.x; st1.y += b1.y; st1.z += b1.z; st1.w += b1.w;
                }
                *(float4*)&O[(size_t)n * H + cg]     = st0;
                *(float4*)&O[(size_t)n * H + cg + 4] = st1;
            }
        }
    }
}

// ---- k_edge: m=ReLU(A[src]+ef@We2+C[dst]); out2=m+ef; scatter mean ----
__global__ __launch_bounds__(NT, 2)
void k_edge(const float* __restrict__ ef,
            const int* __restrict__ src, const int* __restrict__ dst,
            float* __restrict__ out2) {
    extern __shared__ __align__(16) __half sm[];
    __half* sXhi = sm;
    __half* sXlo = sm + TILE_A;                  // lo kept ONLY for out2 = m + ef
    __half* sW   = sm + 2 * TILE_A;
    int*   s_src = (int*)(sm + 2 * TILE_A + TILE_W);
    int*   s_dst = s_src + BT;
    float* stage = (float*)(s_dst + BT);         // 2 x 16 x SSTRIDE
    int t = threadIdx.x, lane = t & 31, warp = t >> 5;

    fill_W(sW, 1, t, NT);                        // We2, resident for all tiles

    int rq = lane >> 2, cb = (warp >> 2) * 64 + (lane & 3) * 2;
    int wr = warp & 3;
    int lrow = t >> 4, cg = (t & 15) * 8;

    int tiles = NTILES - blockIdx.x * TPB;
    if (tiles > TPB) tiles = TPB;

    for (int tt = 0; tt < tiles; tt++) {
        int eb = (blockIdx.x * TPB + tt) * BT;
        if (t < BT) s_src[t] = src[eb + t];
        else if (t < 2 * BT) s_dst[t - BT] = dst[eb + t - BT];
        const float4* ef4 = (const float4*)(ef + (size_t)eb * H);
        for (int i = t; i < BT * 32; i += NT)
            split_store(sXhi, sXlo, (i >> 5) * STRIDE + (i & 31) * 4, ef4[i]);
        __syncthreads();

        // prefetch chunk 0 gathers (hidden under mainloop)
        int s_p = s_src[lrow], d_p = s_dst[lrow];
        float4 pa0 = *(const float4*)&g_A[(size_t)s_p * H + cg];
        float4 pa1 = *(const float4*)&g_A[(size_t)s_p * H + cg + 4];
        float4 pc0 = *(const float4*)&g_C[(size_t)d_p * H + cg];
        float4 pc1 = *(const float4*)&g_C[(size_t)d_p * H + cg + 4];

        float acc[8][4];
#pragma unroll
        for (int i = 0; i < 8; i++) acc[i][0] = acc[i][1] = acc[i][2] = acc[i][3] = 0.f;
        mma_core(sXhi, sW, lane, warp, acc);

#pragma unroll
        for (int c = 0; c < 4; c++) {
            float* stg = stage + (c & 1) * (16 * SSTRIDE);
            stage_chunk(stg, acc, c, wr, rq, cb);
            __syncthreads();                     // stage(c) ready

            int row = c * 16 + lrow;
            int d = d_p;
            if ((t & 15) == 0) atomicAdd(&g_cnt[d], 1.f);

            float4 st0 = *(float4*)&stg[lrow * SSTRIDE + cg];
            float4 st1 = *(float4*)&stg[lrow * SSTRIDE + cg + 4];
            float4 m0, m1;
            m0.x = fmaxf(st0.x + pa0.x + pc0.x, 0.f);
            m0.y = fmaxf(st0.y + pa0.y + pc0.y, 0.f);
            m0.z = fmaxf(st0.z + pa0.z + pc0.z, 0.f);
            m0.w = fmaxf(st0.w + pa0.w + pc0.w, 0.f);
            m1.x = fmaxf(st1.x + pa1.x + pc1.x, 0.f);
            m1.y = fmaxf(st1.y + pa1.y + pc1.y, 0.f);
            m1.z = fmaxf(st1.z + pa1.z + pc1.z, 0.f);
            m1.w = fmaxf(st1.w + pa1.w + pc1.w, 0.f);

            if (c < 3) {                         // next chunk's gathers
                int nrow = (c + 1) * 16 + lrow;
                s_p = s_src[nrow]; d_p = s_dst[nrow];
                pa0 = *(const float4*)&g_A[(size_t)s_p * H + cg];
                pa1 = *(const float4*)&g_A[(size_t)s_p * H + cg + 4];
                pc0 = *(const float4*)&g_C[(size_t)d_p * H + cg];
                pc1 = *(const float4*)&g_C[(size_t)d_p * H + cg + 4];
            }

            // ef reconstruct (hi+lo) from sX, row-major LDS.128
            uint4 uh = *(uint4*)&sXhi[row * STRIDE + cg];
            uint4 ul = *(uint4*)&sXlo[row * STRIDE + cg];
            const __half2* h2 = (const __half2*)&uh;
            const __half2* l2 = (const __half2*)&ul;
            float4 o0, o1;
            o0.x = (m0.x + __half2float(h2[0].x)) + __half2float(l2[0].x);
            o0.y = (m0.y + __half2float(h2[0].y)) + __half2float(l2[0].y);
            o0.z = (m0.z + __half2float(h2[1].x)) + __half2float(l2[1].x);
            o0.w = (m0.w + __half2float(h2[1].y)) + __half2float(l2[1].y);
            o1.x = (m1.x + __half2float(h2[2].x)) + __half2float(l2[2].x);
            o1.y = (m1.y + __half2float(h2[2].y)) + __half2float(l2[2].y);
            o1.z = (m1.z + __half2float(h2[3].x)) + __half2float(l2[3].x);
            o1.w = (m1.w + __half2float(h2[3].y)) + __half2float(l2[3].y);

            *(float4*)&out2[(size_t)(eb + row) * H + cg]     = o0;
            *(float4*)&out2[(size_t)(eb + row) * H + cg + 4] = o1;
            red_add_v4(&g_sum[(size_t)d * H + cg], m0);
            red_add_v4(&g_sum[(size_t)d * H + cg + 4], m1);
        }
        __syncthreads();                         // sX & stage free for next tile
    }
}

// ---- k_node_upd: out1 = ReLU(An + (sum/max(cnt,1))@Wn2) + nf ----
__global__ __launch_bounds__(NT, 2)
void k_node_upd(const float* __restrict__ nf, float* __restrict__ out1) {
    extern __shared__ __align__(16) __half sm[];
    __half* sX = sm;
    __half* sW = sm + TILE_A;
    float* stage = (float*)(sm + TILE_A + TILE_W);
    int t = threadIdx.x, lane = t & 31, warp = t >> 5;
    int nb = blockIdx.x * BT;

    for (int i = t; i < BT * 32; i += NT) {
        int n = nb + (i >> 5);
        float4 v = make_float4(0.f, 0.f, 0.f, 0.f);
        if (n < NNODE) {
            v = ((const float4*)g_sum)[(size_t)n * 32 + (i & 31)];
            float inv = 1.0f / fmaxf(g_cnt[n], 1.0f);
            v.x *= inv; v.y *= inv; v.z *= inv; v.w *= inv;
        }
        store_hi(sX, (i >> 5) * STRIDE + (i & 31) * 4, v);
    }
    fill_W(sW, 4, t, NT);                        // Wn2
    __syncthreads();

    float acc[8][4];
#pragma unroll
    for (int i = 0; i < 8; i++) acc[i][0] = acc[i][1] = acc[i][2] = acc[i][3] = 0.f;
    mma_core(sX, sW, lane, warp, acc);

    int rq = lane >> 2, cb = (warp >> 2) * 64 + (lane & 3) * 2;
    int wr = warp & 3;
    int lrow = t >> 4, cg = (t & 15) * 8;

#pragma unroll
    for (int c = 0; c < 4; c++) {
        float* stg = stage + (c & 1) * (16 * SSTRIDE);
        stage_chunk(stg, acc, c, wr, rq, cb);
        __syncthreads();
        int n = nb + c * 16 + lrow;
        if (n < NNODE) {
            float4 st0 = *(float4*)&stg[lrow * SSTRIDE + cg];
            float4 st1 = *(float4*)&stg[lrow * SSTRIDE + cg + 4];
            float4 an0 = *(const float4*)&g_An[(size_t)n * H + cg];
            float4 an1 = *(const float4*)&g_An[(size_t)n * H + cg + 4];
            float4 nv0 = *(const float4*)&nf[(size_t)n * H + cg];
            float4 nv1 = *(const float4*)&nf[(size_t)n * H + cg + 4];
            float4 o0, o1;
            o0.x = fmaxf(st0.x + an0.x, 0.f) + nv0.x;
            o0.y = fmaxf(st0.y + an0.y, 0.f) + nv0.y;
            o0.z = fmaxf(st0.z + an0.z, 0.f) + nv0.z;
            o0.w = fmaxf(st0.w + an0.w, 0.f) + nv0.w;
            o1.x = fmaxf(st1.x + an1.x, 0.f) + nv1.x;
            o1.y = fmaxf(st1.y + an1.y, 0.f) + nv1.y;
            o1.z = fmaxf(st1.z + an1.z, 0.f) + nv1.z;
            o1.w = fmaxf(st1.w + an1.w, 0.f) + nv1.w;
            *(float4*)&out1[(size_t)n * H + cg]     = o0;
            *(float4*)&out1[(size_t)n * H + cg + 4] = o1;
        }
    }
}

extern "C" void kernel_launch(void* const* d_in, const int* in_sizes, int n_in,
                              void* d_out, int out_size) {
    const float* nf  = (const float*)d_in[0];
    const float* ef  = (const float*)d_in[1];
    const int*   src = (const int*)d_in[2];
    const int*   dst = (const int*)d_in[3];
    const float* We  = (const float*)d_in[4];
    const float* be  = (const float*)d_in[5];
    const float* Wn  = (const float*)d_in[6];
    const float* bn  = (const float*)d_in[7];
    float* out1 = (float*)d_out;                    // [N,H]
    float* out2 = out1 + (size_t)NNODE * H;         // [E,H]

    const int smem_node = (TILE_A + TILE_W) * (int)sizeof(__half)
                        + 2 * 16 * SSTRIDE * (int)sizeof(float);              // 69632
    const int smem_edge = (2 * TILE_A + TILE_W) * (int)sizeof(__half)
                        + 2 * BT * (int)sizeof(int)
                        + 2 * 16 * SSTRIDE * (int)sizeof(float);              // 87552
    cudaFuncSetAttribute(k_node_pre, cudaFuncAttributeMaxDynamicSharedMemorySize, smem_node);
    cudaFuncSetAttribute(k_edge,     cudaFuncAttributeMaxDynamicSharedMemorySize, smem_edge);
    cudaFuncSetAttribute(k_node_upd, cudaFuncAttributeMaxDynamicSharedMemorySize, smem_node);

    k_prep<<<(5 * H * H + 255) / 256, 256>>>(We, Wn);
    k_node_pre<<<(NNODE + BT - 1) / BT, NT, smem_node>>>(nf, be, bn);
    k_edge<<<(NTILES + TPB - 1) / TPB, NT, smem_edge>>>(ef, src, dst, out2);
    k_node_upd<<<(NNODE + BT - 1) / BT, NT, smem_node>>>(nf, out1);
}